// round 1
// baseline (speedup 1.0000x reference)
#include <cuda_runtime.h>
#include <math.h>

// Problem constants
#define BSZ    2
#define TSEQ   2048
#define DK     1024          // per-head dim == d_model
#define HH     4
#define NTOK   (BSZ*TSEQ)    // 4096
#define DPROJ  (HH*DK)       // 4096

// Scratch (static device globals — allocation-free)
__device__ float g_Q[(size_t)NTOK*DPROJ];
__device__ float g_K[(size_t)NTOK*DPROJ];
__device__ float g_V[(size_t)NTOK*DPROJ];
__device__ float g_S[(size_t)BSZ*HH*TSEQ*TSEQ];
__device__ float g_O[(size_t)NTOK*DPROJ];
__device__ float g_X1[(size_t)NTOK*DK];
__device__ float g_Hb[(size_t)NTOK*DK];

// ---------------- Generic tiled SGEMM ----------------
// C[z] = alpha * A[z] (x) op(B[z]) (+ bias) (relu) (+ res)
// A: MxK row-major (lda). B: NN -> KxN row-major (ldb); NT -> NxK row-major (ldb).
// Batch offset: z -> zo = z/innerCount, zi = z%innerCount;  off = zo*sXo + zi*sXi
#define BM 128
#define BN 128
#define BKK 8
#define TM 8
#define TN 8

template<bool TRANSB, bool HAS_BIAS, bool RELU, bool ADD_RES>
__global__ void __launch_bounds__(256)
sgemm_kernel(int M, int N, int Kdim, float alpha,
             const float* __restrict__ A, int lda, long sAo, long sAi,
             const float* __restrict__ B, int ldb, long sBo, long sBi,
             float* __restrict__ C, int ldc, long sCo, long sCi,
             const float* __restrict__ bias,
             const float* __restrict__ Res, int ldres,
             int innerCount, int causal)
{
    // causal skip: only valid when BM==BN and square causal score matrix
    if (causal && (int)blockIdx.x > (int)blockIdx.y) return;

    int z  = blockIdx.z;
    int zo = z / innerCount, zi = z % innerCount;
    A += zo * sAo + (long)zi * sAi;
    B += zo * sBo + (long)zi * sBi;
    C += zo * sCo + (long)zi * sCi;

    __shared__ float As[BKK][BM];
    __shared__ float Bs[BKK][BN];

    const int tid  = threadIdx.x;
    const int brow = blockIdx.y * BM;
    const int bcol = blockIdx.x * BN;
    const int tr   = tid >> 4;        // 0..15
    const int tc   = tid & 15;        // 0..15

    float acc[TM][TN];
    #pragma unroll
    for (int i = 0; i < TM; i++)
        #pragma unroll
        for (int j = 0; j < TN; j++) acc[i][j] = 0.f;

    const int aRow = tid >> 1;          // 0..127
    const int aCol = (tid & 1) * 4;     // 0 or 4

    for (int k0 = 0; k0 < Kdim; k0 += BKK) {
        // --- load A tile (BM x BKK), store transposed ---
        float4 av = *reinterpret_cast<const float4*>(
            &A[(long)(brow + aRow) * lda + k0 + aCol]);
        As[aCol + 0][aRow] = av.x;
        As[aCol + 1][aRow] = av.y;
        As[aCol + 2][aRow] = av.z;
        As[aCol + 3][aRow] = av.w;

        // --- load B tile (BKK x BN) ---
        if (!TRANSB) {
            int bRow = tid >> 5;            // 0..7
            int bCol = (tid & 31) * 4;      // 0..124
            float4 bv = *reinterpret_cast<const float4*>(
                &B[(long)(k0 + bRow) * ldb + bcol + bCol]);
            *reinterpret_cast<float4*>(&Bs[bRow][bCol]) = bv;
        } else {
            int bN = tid >> 1;              // 0..127
            int bK = (tid & 1) * 4;         // 0 or 4
            float4 bv = *reinterpret_cast<const float4*>(
                &B[(long)(bcol + bN) * ldb + k0 + bK]);
            Bs[bK + 0][bN] = bv.x;
            Bs[bK + 1][bN] = bv.y;
            Bs[bK + 2][bN] = bv.z;
            Bs[bK + 3][bN] = bv.w;
        }
        __syncthreads();

        #pragma unroll
        for (int kk = 0; kk < BKK; kk++) {
            float ra[TM], rb[TN];
            *reinterpret_cast<float4*>(&ra[0]) =
                *reinterpret_cast<const float4*>(&As[kk][tr * TM]);
            *reinterpret_cast<float4*>(&ra[4]) =
                *reinterpret_cast<const float4*>(&As[kk][tr * TM + 4]);
            *reinterpret_cast<float4*>(&rb[0]) =
                *reinterpret_cast<const float4*>(&Bs[kk][tc * TN]);
            *reinterpret_cast<float4*>(&rb[4]) =
                *reinterpret_cast<const float4*>(&Bs[kk][tc * TN + 4]);
            #pragma unroll
            for (int i = 0; i < TM; i++)
                #pragma unroll
                for (int j = 0; j < TN; j++)
                    acc[i][j] = fmaf(ra[i], rb[j], acc[i][j]);
        }
        __syncthreads();
    }

    // --- epilogue ---
    #pragma unroll
    for (int i = 0; i < TM; i++) {
        int row = brow + tr * TM + i;
        #pragma unroll
        for (int j = 0; j < TN; j += 4) {
            int col = bcol + tc * TN + j;
            float4 v;
            v.x = alpha * acc[i][j + 0];
            v.y = alpha * acc[i][j + 1];
            v.z = alpha * acc[i][j + 2];
            v.w = alpha * acc[i][j + 3];
            if (HAS_BIAS) {
                v.x += bias[col + 0];
                v.y += bias[col + 1];
                v.z += bias[col + 2];
                v.w += bias[col + 3];
            }
            if (RELU) {
                v.x = fmaxf(v.x, 0.f);
                v.y = fmaxf(v.y, 0.f);
                v.z = fmaxf(v.z, 0.f);
                v.w = fmaxf(v.w, 0.f);
            }
            if (ADD_RES) {
                const float4 r = *reinterpret_cast<const float4*>(
                    &Res[(long)row * ldres + col]);
                v.x += r.x; v.y += r.y; v.z += r.z; v.w += r.w;
            }
            *reinterpret_cast<float4*>(&C[(long)row * ldc + col]) = v;
        }
    }
}

// ---------------- causal row softmax (in place on S) ----------------
__global__ void causal_softmax_kernel(float* __restrict__ S, int T)
{
    const int q = blockIdx.x;
    float* row = S + (long)blockIdx.y * T * T + (long)q * T;
    const int n = q + 1;               // valid columns [0, n)
    const int tid = threadIdx.x;
    const int nthr = blockDim.x;
    __shared__ float sh[32];
    const int lane = tid & 31, wid = tid >> 5, nw = nthr >> 5;

    // max
    float m = -INFINITY;
    for (int j = tid; j < n; j += nthr) m = fmaxf(m, row[j]);
    #pragma unroll
    for (int o = 16; o > 0; o >>= 1) m = fmaxf(m, __shfl_xor_sync(0xffffffffu, m, o));
    if (lane == 0) sh[wid] = m;
    __syncthreads();
    m = (tid < nw) ? sh[tid] : -INFINITY;
    if (wid == 0) {
        #pragma unroll
        for (int o = 16; o > 0; o >>= 1) m = fmaxf(m, __shfl_xor_sync(0xffffffffu, m, o));
        if (lane == 0) sh[0] = m;
    }
    __syncthreads();
    m = sh[0];
    __syncthreads();

    // exp + sum
    float s = 0.f;
    for (int j = tid; j < n; j += nthr) {
        float e = __expf(row[j] - m);
        row[j] = e;
        s += e;
    }
    #pragma unroll
    for (int o = 16; o > 0; o >>= 1) s += __shfl_xor_sync(0xffffffffu, s, o);
    if (lane == 0) sh[wid] = s;
    __syncthreads();
    s = (tid < nw) ? sh[tid] : 0.f;
    if (wid == 0) {
        #pragma unroll
        for (int o = 16; o > 0; o >>= 1) s += __shfl_xor_sync(0xffffffffu, s, o);
        if (lane == 0) sh[0] = s;
    }
    __syncthreads();
    const float inv = 1.f / sh[0];

    for (int j = tid; j < n; j += nthr) row[j] *= inv;
    // zero the masked region so PV can be a dense GEMM
    for (int j = n + tid; j < T; j += nthr) row[j] = 0.f;
}

// ---------------- host launch ----------------
extern "C" void kernel_launch(void* const* d_in, const int* in_sizes, int n_in,
                              void* d_out, int out_size)
{
    (void)in_sizes; (void)n_in; (void)out_size;
    const float* x  = (const float*)d_in[0];
    const float* Wq = (const float*)d_in[1];
    const float* Wk = (const float*)d_in[2];
    const float* Wv = (const float*)d_in[3];
    const float* Wu = (const float*)d_in[4];
    const float* bu = (const float*)d_in[5];
    const float* W1 = (const float*)d_in[6];
    const float* b1 = (const float*)d_in[7];
    const float* W2 = (const float*)d_in[8];
    const float* b2 = (const float*)d_in[9];
    float* out = (float*)d_out;

    float *Q, *Kp, *V, *S, *O, *X1, *Hb;
    cudaGetSymbolAddress((void**)&Q,  g_Q);
    cudaGetSymbolAddress((void**)&Kp, g_K);
    cudaGetSymbolAddress((void**)&V,  g_V);
    cudaGetSymbolAddress((void**)&S,  g_S);
    cudaGetSymbolAddress((void**)&O,  g_O);
    cudaGetSymbolAddress((void**)&X1, g_X1);
    cudaGetSymbolAddress((void**)&Hb, g_Hb);

    const dim3 blk(256);
    const long sTokB = (long)TSEQ * DPROJ;   // batch stride in [b,t,h*k] tensors
    const long sTT   = (long)TSEQ * TSEQ;

    // 1-3. Q/K/V projections: [4096,1024] @ [1024,4096] -> [4096,4096]
    {
        dim3 g(DPROJ / BN, NTOK / BM, 1);
        sgemm_kernel<false,false,false,false><<<g, blk>>>(
            NTOK, DPROJ, DK, 1.f,
            x, DK, 0, 0,  Wq, DPROJ, 0, 0,  Q, DPROJ, 0, 0,
            nullptr, nullptr, 0, 1, 0);
        sgemm_kernel<false,false,false,false><<<g, blk>>>(
            NTOK, DPROJ, DK, 1.f,
            x, DK, 0, 0,  Wk, DPROJ, 0, 0,  Kp, DPROJ, 0, 0,
            nullptr, nullptr, 0, 1, 0);
        sgemm_kernel<false,false,false,false><<<g, blk>>>(
            NTOK, DPROJ, DK, 1.f,
            x, DK, 0, 0,  Wv, DPROJ, 0, 0,  V, DPROJ, 0, 0,
            nullptr, nullptr, 0, 1, 0);
    }

    // 4. S = (1/32) * Q @ K^T per (b,h), causal blocks skipped
    {
        dim3 g(TSEQ / BN, TSEQ / BM, BSZ * HH);
        sgemm_kernel<true,false,false,false><<<g, blk>>>(
            TSEQ, TSEQ, DK, 0.03125f /* k^-0.5 */,
            Q,  DPROJ, sTokB, DK,
            Kp, DPROJ, sTokB, DK,
            S,  TSEQ,  (long)HH * sTT, sTT,
            nullptr, nullptr, 0, HH, 1);
    }

    // 5. causal softmax rows (zeros masked region)
    causal_softmax_kernel<<<dim3(TSEQ, BSZ * HH), 256>>>(S, TSEQ);

    // 6. O = P @ V per (b,h): [2048,2048] @ [2048,1024]
    {
        dim3 g(DK / BN, TSEQ / BM, BSZ * HH);
        sgemm_kernel<false,false,false,false><<<g, blk>>>(
            TSEQ, DK, TSEQ, 1.f,
            S, TSEQ,  (long)HH * sTT, sTT,
            V, DPROJ, sTokB, DK,
            O, DPROJ, sTokB, DK,
            nullptr, nullptr, 0, HH, 0);
    }

    // 7. X1 = x + (O @ Wu + bu)
    {
        dim3 g(DK / BN, NTOK / BM, 1);
        sgemm_kernel<false,true,false,true><<<g, blk>>>(
            NTOK, DK, DPROJ, 1.f,
            O, DPROJ, 0, 0,  Wu, DK, 0, 0,  X1, DK, 0, 0,
            bu, x, DK, 1, 0);
    }

    // 8. Hb = relu(X1 @ W1 + b1)
    {
        dim3 g(DK / BN, NTOK / BM, 1);
        sgemm_kernel<false,true,true,false><<<g, blk>>>(
            NTOK, DK, DK, 1.f,
            X1, DK, 0, 0,  W1, DK, 0, 0,  Hb, DK, 0, 0,
            b1, nullptr, 0, 1, 0);
    }

    // 9. out = X1 + (Hb @ W2 + b2)
    {
        dim3 g(DK / BN, NTOK / BM, 1);
        sgemm_kernel<false,true,false,true><<<g, blk>>>(
            NTOK, DK, DK, 1.f,
            Hb, DK, 0, 0,  W2, DK, 0, 0,  out, DK, 0, 0,
            b2, X1, DK, 1, 0);
    }
}

// round 3
// speedup vs baseline: 6.7609x; 6.7609x over previous
#include <cuda_runtime.h>
#include <cuda_bf16.h>
#include <stdint.h>
#include <math.h>

#define BSZ 2
#define TSEQ 2048
#define DK 1024
#define HH 4
#define NTOK (BSZ*TSEQ)      // 4096
#define DPROJ (HH*DK)        // 4096
typedef __nv_bfloat16 bf16;

// ---------------- scratch (device globals, allocation-free) ----------------
__device__ bf16 g_Xb [(size_t)NTOK*DK];
__device__ bf16 g_Wqb[(size_t)DK*DPROJ];
__device__ bf16 g_Wkb[(size_t)DK*DPROJ];
__device__ bf16 g_Wvb[(size_t)DK*DPROJ];
__device__ bf16 g_Wub[(size_t)DPROJ*DK];
__device__ bf16 g_W1h[(size_t)DK*DK], g_W1l[(size_t)DK*DK];
__device__ bf16 g_W2h[(size_t)DK*DK], g_W2l[(size_t)DK*DK];
__device__ bf16 g_Q[(size_t)NTOK*DPROJ];
__device__ bf16 g_K[(size_t)NTOK*DPROJ];
__device__ bf16 g_V[(size_t)NTOK*DPROJ];
__device__ float g_S[(size_t)BSZ*HH*TSEQ*TSEQ];
__device__ bf16  g_P[(size_t)BSZ*HH*TSEQ*TSEQ];
__device__ bf16 g_O[(size_t)NTOK*DPROJ];
__device__ float g_X1[(size_t)NTOK*DK];
__device__ bf16 g_X1h[(size_t)NTOK*DK], g_X1l[(size_t)NTOK*DK];
__device__ bf16 g_Hh[(size_t)NTOK*DK],  g_Hl[(size_t)NTOK*DK];

// ---------------- PTX helpers (baseline ISA only — no tcgen05) ----------------
static __device__ __forceinline__ uint32_t s2u(const void* p){
    uint32_t a;
    asm("{ .reg .u64 t; cvta.to.shared.u64 t, %1; cvt.u32.u64 %0, t; }" : "=r"(a) : "l"(p));
    return a;
}
static __device__ __forceinline__ void cpasync16(uint32_t dst, const void* src){
    asm volatile("cp.async.cg.shared.global [%0], [%1], 16;"
                 :: "r"(dst), "l"(__cvta_generic_to_global(src)) : "memory");
}
static __device__ __forceinline__ void cp_commit(){
    asm volatile("cp.async.commit_group;" ::: "memory");
}
static __device__ __forceinline__ void cp_wait0(){
    asm volatile("cp.async.wait_group 0;" ::: "memory");
}
static __device__ __forceinline__ void ldsm4(uint32_t* r, uint32_t a){
    asm volatile("ldmatrix.sync.aligned.m8n8.x4.shared.b16 {%0,%1,%2,%3}, [%4];"
                 : "=r"(r[0]),"=r"(r[1]),"=r"(r[2]),"=r"(r[3]) : "r"(a));
}
static __device__ __forceinline__ void ldsm4t(uint32_t* r, uint32_t a){
    asm volatile("ldmatrix.sync.aligned.m8n8.x4.trans.shared.b16 {%0,%1,%2,%3}, [%4];"
                 : "=r"(r[0]),"=r"(r[1]),"=r"(r[2]),"=r"(r[3]) : "r"(a));
}
static __device__ __forceinline__ void mma16816(float* c, const uint32_t* a, const uint32_t* b){
    asm volatile(
        "mma.sync.aligned.m16n8k16.row.col.f32.bf16.bf16.f32 "
        "{%0,%1,%2,%3}, {%4,%5,%6,%7}, {%8,%9}, {%0,%1,%2,%3};"
        : "+f"(c[0]),"+f"(c[1]),"+f"(c[2]),"+f"(c[3])
        : "r"(a[0]),"r"(a[1]),"r"(a[2]),"r"(a[3]), "r"(b[0]),"r"(b[1]));
}
static __device__ __forceinline__ void split2(float v, bf16& h, bf16& l){
    h = __float2bfloat16(v);
    l = __float2bfloat16(v - __bfloat162float(h));
}

// ---------------- conversion kernels ----------------
__global__ void split_bf(const float* __restrict__ in, bf16* __restrict__ o, int n4){
    int i = blockIdx.x*blockDim.x + threadIdx.x;
    if (i >= n4) return;
    float4 v = reinterpret_cast<const float4*>(in)[i];
    __nv_bfloat162 a, b;
    a.x = __float2bfloat16(v.x); a.y = __float2bfloat16(v.y);
    b.x = __float2bfloat16(v.z); b.y = __float2bfloat16(v.w);
    reinterpret_cast<__nv_bfloat162*>(o)[2*i]   = a;
    reinterpret_cast<__nv_bfloat162*>(o)[2*i+1] = b;
}
__global__ void split_hl(const float* __restrict__ in, bf16* __restrict__ oh,
                         bf16* __restrict__ ol, int n4){
    int i = blockIdx.x*blockDim.x + threadIdx.x;
    if (i >= n4) return;
    float4 v = reinterpret_cast<const float4*>(in)[i];
    bf16 h0,h1,h2,h3,l0,l1,l2,l3;
    split2(v.x,h0,l0); split2(v.y,h1,l1); split2(v.z,h2,l2); split2(v.w,h3,l3);
    __nv_bfloat162 ha, hb, la, lb;
    ha.x=h0; ha.y=h1; hb.x=h2; hb.y=h3;
    la.x=l0; la.y=l1; lb.x=l2; lb.y=l3;
    reinterpret_cast<__nv_bfloat162*>(oh)[2*i]   = ha;
    reinterpret_cast<__nv_bfloat162*>(oh)[2*i+1] = hb;
    reinterpret_cast<__nv_bfloat162*>(ol)[2*i]   = la;
    reinterpret_cast<__nv_bfloat162*>(ol)[2*i+1] = lb;
}

// ---------------- mma.sync GEMM ----------------
// C = alpha * (A)(B) (+bias)(relu)(+res)
// A: [M,K] bf16 row-major.
// TRB=false: B given as [N,K] row-major (NT). TRB=true: B given as [K,N] row-major.
// PASSES=3: hi/lo emulation (Ah*Bh + Ah*Bl + Al*Bh), fp32 accum.
// OUTM: 0 = bf16 (Ch); 1 = fp32 (Cf); 2 = fp32 + bf16 hi/lo.
#define TILEB 16384   // one 128x64 (or 64x128) bf16 tile

template<int PASSES, bool TRB, int OUTM, bool BIASF, bool RELUF, bool RESF, bool CSKIP, bool CK>
__global__ void __launch_bounds__(256,1)
gmma(int Kdim, float alpha,
     const bf16* __restrict__ Ah, const bf16* __restrict__ Al, int lda, long sAo, long sAi,
     const bf16* __restrict__ Bh, const bf16* __restrict__ Bl, int ldb, long sBo, long sBi,
     float* __restrict__ Cf, bf16* __restrict__ Ch, bf16* __restrict__ Cl,
     int ldc, long sCo, long sCi,
     const float* __restrict__ bias, const float* __restrict__ Res, int ldres,
     int innerCount)
{
    if (CSKIP && blockIdx.x > blockIdx.y) return;

    extern __shared__ char smem[];
    const uint32_t sb = s2u(smem);
    const int tid = threadIdx.x, wid = tid >> 5, lane = tid & 31;
    const int wm0 = (wid >> 2) * 64;    // warp row offset in CTA tile
    const int wn0 = (wid & 3) * 32;     // warp col offset

    const int z = blockIdx.z, zo = z / innerCount, zi = z - zo * innerCount;
    Ah += zo*sAo + (long)zi*sAi;  if (PASSES==3) Al += zo*sAo + (long)zi*sAi;
    Bh += zo*sBo + (long)zi*sBi;  if (PASSES==3) Bl += zo*sBo + (long)zi*sBi;
    const long coff = zo*sCo + (long)zi*sCi;

    const int brow = blockIdx.y * 128, bcol = blockIdx.x * 128;
    const int kEnd = CK ? (blockIdx.y + 1) * 128 : Kdim;
    const int NITER = kEnd >> 6;

    const int nT = (PASSES==3) ? 4 : 2;
    const uint32_t stageB = nT * TILEB;

    // ---- loaders ----
    auto ldTile = [&](const bf16* g, int ld, int r0, int k0, uint32_t so){
        #pragma unroll
        for (int i = 0; i < 4; i++){
            int idx = i*256 + tid;
            int row = idx >> 3, c = idx & 7;
            cpasync16(sb + so + row*128 + (((c ^ (row&7)))<<4),
                      g + (long)(r0+row)*ld + k0 + c*8);
        }
    };
    auto ldTileT = [&](const bf16* g, int ld, int c0, int k0, uint32_t so){
        #pragma unroll
        for (int i = 0; i < 4; i++){
            int idx = i*256 + tid;
            int row = idx >> 4, c = idx & 15;
            cpasync16(sb + so + row*256 + (((c ^ (row&7)))<<4),
                      g + (long)(k0+row)*ld + c0 + c*8);
        }
    };
    auto loadStage = [&](int s, int k0){
        uint32_t so = s * stageB;
        ldTile(Ah, lda, brow, k0, so);
        if (PASSES==3) ldTile(Al, lda, brow, k0, so + TILEB);
        uint32_t bo = so + (PASSES==3 ? 2 : 1) * TILEB;
        if (TRB){
            ldTileT(Bh, ldb, bcol, k0, bo);
            if (PASSES==3) ldTileT(Bl, ldb, bcol, k0, bo + TILEB);
        } else {
            ldTile(Bh, ldb, bcol, k0, bo);
            if (PASSES==3) ldTile(Bl, ldb, bcol, k0, bo + TILEB);
        }
        cp_commit();
    };

    // ---- per-thread ldmatrix address components ----
    // A: rows wm0 + mq*16 + (lane&15); k-half by (lane>>4)&1
    uint32_t aRow[4], aS[4];
    const int akb = (lane >> 4) & 1;
    #pragma unroll
    for (int mq = 0; mq < 4; mq++){
        int r = wm0 + mq*16 + (lane & 15);
        aRow[mq] = r * 128; aS[mq] = r & 7;
    }
    // B non-trans: rows wn0 + nq2*16 + (lane&7) + ((lane&16)?8:0); k-half by (lane>>3)&1
    uint32_t bRow[2], bS[2];
    const int bkb = (lane >> 3) & 1;
    #pragma unroll
    for (int nq = 0; nq < 2; nq++){
        int r = wn0 + nq*16 + (lane & 7) + ((lane & 16) ? 8 : 0);
        bRow[nq] = r * 128; bS[nq] = r & 7;
    }
    // B trans: k-row = ks*16 + (lane&15); n-chunk = wn0/8 + nq*2 + ((lane>>4)&1)
    const int tKr = lane & 15;
    uint32_t tCk[2];
    #pragma unroll
    for (int nq = 0; nq < 2; nq++)
        tCk[nq] = (wn0 >> 3) + nq*2 + ((lane >> 4) & 1);

    float acc[4][4][4];
    #pragma unroll
    for (int a = 0; a < 4; a++)
        #pragma unroll
        for (int b = 0; b < 4; b++)
            #pragma unroll
            for (int c = 0; c < 4; c++) acc[a][b][c] = 0.f;

    auto compute = [&](int s){
        const uint32_t Ab  = sb + s*stageB;
        const uint32_t Alb = Ab + TILEB;
        const uint32_t Bb  = Ab + (PASSES==3 ? 2 : 1)*TILEB;
        const uint32_t Blb = Bb + TILEB;
        #pragma unroll
        for (int ks = 0; ks < 4; ks++){
            uint32_t ah[4][4], bh[8];
            #pragma unroll
            for (int mq = 0; mq < 4; mq++)
                ldsm4(ah[mq], Ab + aRow[mq] + ((uint32_t)((ks*2 + akb) ^ aS[mq]) << 4));
            if (TRB){
                const int kr = ks*16 + tKr;
                #pragma unroll
                for (int nq = 0; nq < 2; nq++)
                    ldsm4t(&bh[nq*4], Bb + kr*256 + ((tCk[nq] ^ (uint32_t)(kr & 7)) << 4));
            } else {
                #pragma unroll
                for (int nq = 0; nq < 2; nq++)
                    ldsm4(&bh[nq*4], Bb + bRow[nq] + ((uint32_t)((ks*2 + bkb) ^ bS[nq]) << 4));
            }
            #pragma unroll
            for (int mf = 0; mf < 4; mf++)
                #pragma unroll
                for (int nf = 0; nf < 4; nf++)
                    mma16816(acc[mf][nf], ah[mf], &bh[(nf>>1)*4 + (nf&1)*2]);

            if (PASSES == 3){
                uint32_t bl[8];
                if (TRB){
                    const int kr = ks*16 + tKr;
                    #pragma unroll
                    for (int nq = 0; nq < 2; nq++)
                        ldsm4t(&bl[nq*4], Blb + kr*256 + ((tCk[nq] ^ (uint32_t)(kr & 7)) << 4));
                } else {
                    #pragma unroll
                    for (int nq = 0; nq < 2; nq++)
                        ldsm4(&bl[nq*4], Blb + bRow[nq] + ((uint32_t)((ks*2 + bkb) ^ bS[nq]) << 4));
                }
                #pragma unroll
                for (int mf = 0; mf < 4; mf++)
                    #pragma unroll
                    for (int nf = 0; nf < 4; nf++)
                        mma16816(acc[mf][nf], ah[mf], &bl[(nf>>1)*4 + (nf&1)*2]);
                uint32_t al[4][4];
                #pragma unroll
                for (int mq = 0; mq < 4; mq++)
                    ldsm4(al[mq], Alb + aRow[mq] + ((uint32_t)((ks*2 + akb) ^ aS[mq]) << 4));
                #pragma unroll
                for (int mf = 0; mf < 4; mf++)
                    #pragma unroll
                    for (int nf = 0; nf < 4; nf++)
                        mma16816(acc[mf][nf], al[mf], &bh[(nf>>1)*4 + (nf&1)*2]);
            }
        }
    };

    // ---- pipelined mainloop ----
    loadStage(0, 0);
    for (int it = 0; it < NITER; ++it){
        cp_wait0();
        __syncthreads();
        if (it + 1 < NITER) loadStage((it+1) & 1, (it+1)*64);
        compute(it & 1);
    }

    // ---- epilogue ----
    if (Cf) Cf += coff;
    if (Ch) Ch += coff;
    if (Cl) Cl += coff;
    #pragma unroll
    for (int mf = 0; mf < 4; mf++){
        const int r = brow + wm0 + mf*16 + (lane >> 2);
        #pragma unroll
        for (int nf = 0; nf < 4; nf++){
            const int c = bcol + wn0 + nf*8 + (lane & 3)*2;
            float v[4];
            #pragma unroll
            for (int q = 0; q < 4; q++) v[q] = alpha * acc[mf][nf][q];
            if (BIASF){
                const float b0 = __ldg(bias + c), b1 = __ldg(bias + c + 1);
                v[0] += b0; v[1] += b1; v[2] += b0; v[3] += b1;
            }
            if (RELUF){
                #pragma unroll
                for (int q = 0; q < 4; q++) v[q] = fmaxf(v[q], 0.f);
            }
            if (RESF){
                v[0] += __ldg(Res + (long)r*ldres + c);
                v[1] += __ldg(Res + (long)r*ldres + c + 1);
                v[2] += __ldg(Res + (long)(r+8)*ldres + c);
                v[3] += __ldg(Res + (long)(r+8)*ldres + c + 1);
            }
            #pragma unroll
            for (int half = 0; half < 2; half++){
                const long o = (long)(r + half*8) * ldc + c;
                const float x0 = v[half*2], x1 = v[half*2 + 1];
                if (OUTM == 1){
                    float2 f; f.x = x0; f.y = x1;
                    *reinterpret_cast<float2*>(Cf + o) = f;
                } else if (OUTM == 0){
                    __nv_bfloat162 p;
                    p.x = __float2bfloat16(x0); p.y = __float2bfloat16(x1);
                    *reinterpret_cast<__nv_bfloat162*>(Ch + o) = p;
                } else {
                    float2 f; f.x = x0; f.y = x1;
                    *reinterpret_cast<float2*>(Cf + o) = f;
                    bf16 h0,l0,h1,l1;
                    split2(x0,h0,l0); split2(x1,h1,l1);
                    __nv_bfloat162 ph, pl;
                    ph.x = h0; ph.y = h1; pl.x = l0; pl.y = l1;
                    *reinterpret_cast<__nv_bfloat162*>(Ch + o) = ph;
                    *reinterpret_cast<__nv_bfloat162*>(Cl + o) = pl;
                }
            }
        }
    }
}

// ---------------- causal softmax: S fp32 -> P bf16 (masked region zeroed) ----
__global__ void causal_softmax_kernel(const float* __restrict__ S,
                                      bf16* __restrict__ P, int T)
{
    const int q = blockIdx.x;
    const long ro = ((long)blockIdx.y * T + q) * T;
    const float* row = S + ro;
    const int n = q + 1;
    const int tid = threadIdx.x, nthr = blockDim.x;
    __shared__ float sh[32];
    const int lane = tid & 31, wid = tid >> 5, nw = nthr >> 5;

    float m = -INFINITY;
    for (int j = tid; j < n; j += nthr) m = fmaxf(m, row[j]);
    #pragma unroll
    for (int o = 16; o > 0; o >>= 1) m = fmaxf(m, __shfl_xor_sync(0xffffffffu, m, o));
    if (lane == 0) sh[wid] = m;
    __syncthreads();
    m = (tid < nw) ? sh[tid] : -INFINITY;
    if (wid == 0){
        #pragma unroll
        for (int o = 16; o > 0; o >>= 1) m = fmaxf(m, __shfl_xor_sync(0xffffffffu, m, o));
        if (lane == 0) sh[0] = m;
    }
    __syncthreads();
    m = sh[0];
    __syncthreads();

    float s = 0.f;
    for (int j = tid; j < n; j += nthr) s += __expf(row[j] - m);
    #pragma unroll
    for (int o = 16; o > 0; o >>= 1) s += __shfl_xor_sync(0xffffffffu, s, o);
    if (lane == 0) sh[wid] = s;
    __syncthreads();
    s = (tid < nw) ? sh[tid] : 0.f;
    if (wid == 0){
        #pragma unroll
        for (int o = 16; o > 0; o >>= 1) s += __shfl_xor_sync(0xffffffffu, s, o);
        if (lane == 0) sh[0] = s;
    }
    __syncthreads();
    const float inv = 1.f / sh[0];

    for (int j = tid; j < n; j += nthr)
        P[ro + j] = __float2bfloat16(__expf(row[j] - m) * inv);
    const bf16 z = __float2bfloat16(0.f);
    for (int j = n + tid; j < T; j += nthr) P[ro + j] = z;
}

// ---------------- host ----------------
#define GETB(sym, var) bf16* var; cudaGetSymbolAddress((void**)&var, sym)

extern "C" void kernel_launch(void* const* d_in, const int* in_sizes, int n_in,
                              void* d_out, int out_size)
{
    (void)in_sizes; (void)n_in; (void)out_size;
    const float* x  = (const float*)d_in[0];
    const float* Wq = (const float*)d_in[1];
    const float* Wk = (const float*)d_in[2];
    const float* Wv = (const float*)d_in[3];
    const float* Wu = (const float*)d_in[4];
    const float* bu = (const float*)d_in[5];
    const float* W1 = (const float*)d_in[6];
    const float* b1 = (const float*)d_in[7];
    const float* W2 = (const float*)d_in[8];
    const float* b2 = (const float*)d_in[9];
    float* out = (float*)d_out;

    GETB(g_Xb,Xb);
    GETB(g_Wqb,Wqb); GETB(g_Wkb,Wkb); GETB(g_Wvb,Wvb); GETB(g_Wub,Wub);
    GETB(g_W1h,W1h); GETB(g_W1l,W1l); GETB(g_W2h,W2h); GETB(g_W2l,W2l);
    GETB(g_Q,Q); GETB(g_K,Kb); GETB(g_V,V);
    GETB(g_P,P); GETB(g_O,O);
    GETB(g_X1h,X1h); GETB(g_X1l,X1l); GETB(g_Hh,Hh); GETB(g_Hl,Hl);
    float *S, *X1;
    cudaGetSymbolAddress((void**)&S,  g_S);
    cudaGetSymbolAddress((void**)&X1, g_X1);

    // instantiations
    auto gProj = gmma<1,true ,0,false,false,false,false,false>; // X@W -> bf16
    auto gS    = gmma<1,false,1,false,false,false,true ,false>; // QK^T -> fp32, causal skip
    auto gPV   = gmma<1,true ,0,false,false,false,false,true >; // P@V -> bf16, causal K bound
    auto gWu   = gmma<1,true ,2,true ,false,true ,false,false>; // O@Wu+bu+x -> fp32 + h/l
    auto gF1   = gmma<3,true ,0,true ,true ,false,false,false>; // relu(X1@W1+b1) -> h/l (3-pass)
    auto gF2   = gmma<3,true ,1,true ,false,true ,false,false>; // X1 + H@W2+b2 -> fp32 (3-pass)

    const int SM1 = 2*2*TILEB;   // 64 KB
    const int SM3 = 2*4*TILEB;   // 128 KB
    cudaFuncSetAttribute(gProj, cudaFuncAttributeMaxDynamicSharedMemorySize, SM1);
    cudaFuncSetAttribute(gS   , cudaFuncAttributeMaxDynamicSharedMemorySize, SM1);
    cudaFuncSetAttribute(gPV  , cudaFuncAttributeMaxDynamicSharedMemorySize, SM1);
    cudaFuncSetAttribute(gWu  , cudaFuncAttributeMaxDynamicSharedMemorySize, SM1);
    cudaFuncSetAttribute(gF1  , cudaFuncAttributeMaxDynamicSharedMemorySize, SM3);
    cudaFuncSetAttribute(gF2  , cudaFuncAttributeMaxDynamicSharedMemorySize, SM3);

    // ---- 0. dtype conversions ----
    split_bf<<<(NTOK*DK/4 + 255)/256, 256>>>(x,  Xb,  NTOK*DK/4);
    split_bf<<<(DK*DPROJ/4 + 255)/256, 256>>>(Wq, Wqb, DK*DPROJ/4);
    split_bf<<<(DK*DPROJ/4 + 255)/256, 256>>>(Wk, Wkb, DK*DPROJ/4);
    split_bf<<<(DK*DPROJ/4 + 255)/256, 256>>>(Wv, Wvb, DK*DPROJ/4);
    split_bf<<<(DPROJ*DK/4 + 255)/256, 256>>>(Wu, Wub, DPROJ*DK/4);
    split_hl<<<(DK*DK/4 + 255)/256, 256>>>(W1, W1h, W1l, DK*DK/4);
    split_hl<<<(DK*DK/4 + 255)/256, 256>>>(W2, W2h, W2l, DK*DK/4);

    const long sTT = (long)TSEQ*TSEQ;

    // ---- 1. Q, K, V projections: [4096,1024] @ [1024,4096] ----
    {
        dim3 g(DPROJ/128, NTOK/128, 1);
        gProj<<<g, 256, SM1>>>(DK, 1.f, Xb, nullptr, DK, 0, 0,
                               Wqb, nullptr, DPROJ, 0, 0,
                               nullptr, Q, nullptr, DPROJ, 0, 0,
                               nullptr, nullptr, 0, 1);
        gProj<<<g, 256, SM1>>>(DK, 1.f, Xb, nullptr, DK, 0, 0,
                               Wkb, nullptr, DPROJ, 0, 0,
                               nullptr, Kb, nullptr, DPROJ, 0, 0,
                               nullptr, nullptr, 0, 1);
        gProj<<<g, 256, SM1>>>(DK, 1.f, Xb, nullptr, DK, 0, 0,
                               Wvb, nullptr, DPROJ, 0, 0,
                               nullptr, V, nullptr, DPROJ, 0, 0,
                               nullptr, nullptr, 0, 1);
    }

    // ---- 2. S = (1/32) Q K^T per (b,h), causal block skip ----
    gS<<<dim3(TSEQ/128, TSEQ/128, BSZ*HH), 256, SM1>>>(
        DK, 0.03125f,
        Q,  nullptr, DPROJ, (long)TSEQ*DPROJ, DK,
        Kb, nullptr, DPROJ, (long)TSEQ*DPROJ, DK,
        S, nullptr, nullptr, TSEQ, (long)HH*sTT, sTT,
        nullptr, nullptr, 0, HH);

    // ---- 3. softmax -> P bf16 ----
    causal_softmax_kernel<<<dim3(TSEQ, BSZ*HH), 256>>>(S, P, TSEQ);

    // ---- 4. O = P @ V per (b,h), causal K bound (B = V [t,d], TRB) ----
    gPV<<<dim3(DK/128, TSEQ/128, BSZ*HH), 256, SM1>>>(
        TSEQ, 1.f,
        P, nullptr, TSEQ, (long)HH*sTT, sTT,
        V, nullptr, DPROJ, (long)TSEQ*DPROJ, DK,
        nullptr, O, nullptr, DPROJ, (long)TSEQ*DPROJ, DK,
        nullptr, nullptr, 0, HH);

    // ---- 5. X1 = x + O@Wu + bu  (fp32 + hi/lo) ----
    gWu<<<dim3(DK/128, NTOK/128, 1), 256, SM1>>>(
        DPROJ, 1.f, O, nullptr, DPROJ, 0, 0,
        Wub, nullptr, DK, 0, 0,
        X1, X1h, X1l, DK, 0, 0, bu, x, DK, 1);

    // ---- 6. H = relu(X1@W1 + b1)  (3-pass) ----
    gF1<<<dim3(DK/128, NTOK/128, 1), 256, SM3>>>(
        DK, 1.f, X1h, X1l, DK, 0, 0,
        W1h, W1l, DK, 0, 0,
        nullptr, Hh, Hl, DK, 0, 0, b1, nullptr, 0, 1);

    // ---- 7. out = X1 + H@W2 + b2  (3-pass) ----
    gF2<<<dim3(DK/128, NTOK/128, 1), 256, SM3>>>(
        DK, 1.f, Hh, Hl, DK, 0, 0,
        W2h, W2l, DK, 0, 0,
        out, nullptr, nullptr, DK, 0, 0, b2, X1, DK, 1);
}

// round 5
// speedup vs baseline: 7.2787x; 1.0766x over previous
#include <cuda_runtime.h>
#include <cuda_bf16.h>
#include <stdint.h>
#include <math.h>

#define BSZ 2
#define TSEQ 2048
#define DK 1024
#define HH 4
#define NTOK (BSZ*TSEQ)      // 4096
#define DPROJ (HH*DK)        // 4096
typedef __nv_bfloat16 bf16;

// ---------------- scratch (device globals, allocation-free) ----------------
__device__ bf16 g_Xb [(size_t)NTOK*DK];
__device__ bf16 g_Wqb[(size_t)DK*DPROJ];
__device__ bf16 g_Wkb[(size_t)DK*DPROJ];
__device__ bf16 g_Wvb[(size_t)DK*DPROJ];
__device__ bf16 g_Wub[(size_t)DPROJ*DK];
__device__ bf16 g_W1h[(size_t)DK*DK], g_W1l[(size_t)DK*DK];
__device__ bf16 g_W2h[(size_t)DK*DK], g_W2l[(size_t)DK*DK];
__device__ bf16 g_Q[(size_t)NTOK*DPROJ];
__device__ bf16 g_K[(size_t)NTOK*DPROJ];
__device__ bf16 g_V[(size_t)NTOK*DPROJ];
__device__ float g_S[(size_t)BSZ*HH*TSEQ*TSEQ];
__device__ bf16  g_P[(size_t)BSZ*HH*TSEQ*TSEQ];
__device__ bf16 g_O[(size_t)NTOK*DPROJ];
__device__ float g_X1[(size_t)NTOK*DK];
__device__ bf16 g_X1h[(size_t)NTOK*DK], g_X1l[(size_t)NTOK*DK];
__device__ bf16 g_Hh[(size_t)NTOK*DK],  g_Hl[(size_t)NTOK*DK];

// ---------------- PTX helpers ----------------
static __device__ __forceinline__ uint32_t s2u(const void* p){
    uint32_t a;
    asm("{ .reg .u64 t; cvta.to.shared.u64 t, %1; cvt.u32.u64 %0, t; }" : "=r"(a) : "l"(p));
    return a;
}
static __device__ __forceinline__ void cpasync16(uint32_t dst, const void* src){
    asm volatile("cp.async.cg.shared.global [%0], [%1], 16;"
                 :: "r"(dst), "l"(__cvta_generic_to_global(src)) : "memory");
}
static __device__ __forceinline__ void cp_commit(){
    asm volatile("cp.async.commit_group;" ::: "memory");
}
template<int N>
static __device__ __forceinline__ void cp_wait(){
    asm volatile("cp.async.wait_group %0;" :: "n"(N) : "memory");
}
static __device__ __forceinline__ void ldsm4(uint32_t* r, uint32_t a){
    asm volatile("ldmatrix.sync.aligned.m8n8.x4.shared.b16 {%0,%1,%2,%3}, [%4];"
                 : "=r"(r[0]),"=r"(r[1]),"=r"(r[2]),"=r"(r[3]) : "r"(a));
}
static __device__ __forceinline__ void ldsm4t(uint32_t* r, uint32_t a){
    asm volatile("ldmatrix.sync.aligned.m8n8.x4.trans.shared.b16 {%0,%1,%2,%3}, [%4];"
                 : "=r"(r[0]),"=r"(r[1]),"=r"(r[2]),"=r"(r[3]) : "r"(a));
}
static __device__ __forceinline__ void mma16816(float* c, const uint32_t* a, const uint32_t* b){
    asm volatile(
        "mma.sync.aligned.m16n8k16.row.col.f32.bf16.bf16.f32 "
        "{%0,%1,%2,%3}, {%4,%5,%6,%7}, {%8,%9}, {%0,%1,%2,%3};"
        : "+f"(c[0]),"+f"(c[1]),"+f"(c[2]),"+f"(c[3])
        : "r"(a[0]),"r"(a[1]),"r"(a[2]),"r"(a[3]), "r"(b[0]),"r"(b[1]));
}
static __device__ __forceinline__ void split2(float v, bf16& h, bf16& l){
    h = __float2bfloat16(v);
    l = __float2bfloat16(v - __bfloat162float(h));
}

// ---------------- fused conversion kernels ----------------
// 5 segments x 4M fp32 elems -> bf16.  256 blocks/segment, 16 float4/thread.
__global__ void __launch_bounds__(256)
conv5(const float* __restrict__ s0, bf16* __restrict__ d0,
      const float* __restrict__ s1, bf16* __restrict__ d1,
      const float* __restrict__ s2, bf16* __restrict__ d2,
      const float* __restrict__ s3, bf16* __restrict__ d3,
      const float* __restrict__ s4, bf16* __restrict__ d4)
{
    const int seg = blockIdx.x >> 8, b = blockIdx.x & 255;
    const float* s; bf16* d;
    switch (seg){
        case 0: s = s0; d = d0; break;
        case 1: s = s1; d = d1; break;
        case 2: s = s2; d = d2; break;
        case 3: s = s3; d = d3; break;
        default: s = s4; d = d4; break;
    }
    const int base = b * (256*16);
    #pragma unroll 4
    for (int i = 0; i < 16; i++){
        int idx = base + i*256 + threadIdx.x;
        float4 v = reinterpret_cast<const float4*>(s)[idx];
        __nv_bfloat162 a, c;
        a.x = __float2bfloat16(v.x); a.y = __float2bfloat16(v.y);
        c.x = __float2bfloat16(v.z); c.y = __float2bfloat16(v.w);
        reinterpret_cast<__nv_bfloat162*>(d)[2*idx]   = a;
        reinterpret_cast<__nv_bfloat162*>(d)[2*idx+1] = c;
    }
}
// 2 segments x 1M fp32 elems -> bf16 hi/lo.  64 blocks/segment, 16 float4/thread.
__global__ void __launch_bounds__(256)
conv_hl2(const float* __restrict__ s0, bf16* __restrict__ h0, bf16* __restrict__ l0,
         const float* __restrict__ s1, bf16* __restrict__ h1, bf16* __restrict__ l1)
{
    const int seg = blockIdx.x >> 6, b = blockIdx.x & 63;
    const float* s = seg ? s1 : s0;
    bf16* dh = seg ? h1 : h0;
    bf16* dl = seg ? l1 : l0;
    const int base = b * (256*16);
    #pragma unroll 4
    for (int i = 0; i < 16; i++){
        int idx = base + i*256 + threadIdx.x;
        float4 v = reinterpret_cast<const float4*>(s)[idx];
        bf16 a0,a1,a2,a3,c0,c1,c2,c3;
        split2(v.x,a0,c0); split2(v.y,a1,c1); split2(v.z,a2,c2); split2(v.w,a3,c3);
        __nv_bfloat162 ha, hb, la, lb;
        ha.x=a0; ha.y=a1; hb.x=a2; hb.y=a3;
        la.x=c0; la.y=c1; lb.x=c2; lb.y=c3;
        reinterpret_cast<__nv_bfloat162*>(dh)[2*idx]   = ha;
        reinterpret_cast<__nv_bfloat162*>(dh)[2*idx+1] = hb;
        reinterpret_cast<__nv_bfloat162*>(dl)[2*idx]   = la;
        reinterpret_cast<__nv_bfloat162*>(dl)[2*idx+1] = lb;
    }
}

// ---------------- mma.sync GEMM ----------------
// C = alpha * (A)(B) (+bias)(relu)(+res)
// A: [M,K] bf16 row-major.
// TRB=false: B given as [N,K] row-major (NT). TRB=true: B given as [K,N] row-major.
// PASSES=3: hi/lo emulation (Ah*Bh + Ah*Bl + Al*Bh), fp32 accum.
// OUTM: 0 = bf16 (Ch); 1 = fp32 (Cf); 2 = fp32 + bf16 hi/lo.
// NSEL=3: blockIdx.z selects among {Bh,Bh2,Bh3} / {Ch,Ch2,Ch3} (fused QKV).
// STAGES: cp.async pipeline depth.
#define TILEB 16384   // one 128x64 (or 64x128) bf16 tile

template<int PASSES, bool TRB, int OUTM, bool BIASF, bool RELUF, bool RESF,
         bool CSKIP, bool CK, int NSEL, int STAGES>
__global__ void __launch_bounds__(256,1)
gmma(int Kdim, float alpha,
     const bf16* __restrict__ Ah, const bf16* __restrict__ Al, int lda, long sAo, long sAi,
     const bf16* __restrict__ Bh, const bf16* __restrict__ Bl, int ldb, long sBo, long sBi,
     const bf16* __restrict__ Bh2, const bf16* __restrict__ Bh3,
     float* __restrict__ Cf, bf16* __restrict__ Ch, bf16* __restrict__ Cl,
     bf16* __restrict__ Ch2, bf16* __restrict__ Ch3,
     int ldc, long sCo, long sCi,
     const float* __restrict__ bias, const float* __restrict__ Res, int ldres,
     int innerCount)
{
    if (CSKIP && blockIdx.x > blockIdx.y) return;

    extern __shared__ char smem[];
    const uint32_t sb = s2u(smem);
    const int tid = threadIdx.x, wid = tid >> 5, lane = tid & 31;
    const int wm0 = (wid >> 2) * 64;
    const int wn0 = (wid & 3) * 32;

    if (NSEL == 3){
        const int sel = blockIdx.z;
        if (sel == 1){ Bh = Bh2; Ch = Ch2; }
        else if (sel == 2){ Bh = Bh3; Ch = Ch3; }
    } else {
        const int z = blockIdx.z, zo = z / innerCount, zi = z - zo * innerCount;
        Ah += zo*sAo + (long)zi*sAi;  if (PASSES==3) Al += zo*sAo + (long)zi*sAi;
        Bh += zo*sBo + (long)zi*sBi;  if (PASSES==3) Bl += zo*sBo + (long)zi*sBi;
        const long coff = zo*sCo + (long)zi*sCi;
        if (Cf) Cf += coff;
        if (Ch) Ch += coff;
        if (Cl) Cl += coff;
    }

    const int brow = blockIdx.y * 128, bcol = blockIdx.x * 128;
    const int kEnd = CK ? (blockIdx.y + 1) * 128 : Kdim;
    const int NITER = kEnd >> 6;

    const uint32_t stageB = (PASSES==3 ? 4 : 2) * TILEB;

    // ---- loaders ----
    auto ldTile = [&](const bf16* g, int ld, int r0, int k0, uint32_t so){
        #pragma unroll
        for (int i = 0; i < 4; i++){
            int idx = i*256 + tid;
            int row = idx >> 3, c = idx & 7;
            cpasync16(sb + so + row*128 + (((c ^ (row&7)))<<4),
                      g + (long)(r0+row)*ld + k0 + c*8);
        }
    };
    auto ldTileT = [&](const bf16* g, int ld, int c0, int k0, uint32_t so){
        #pragma unroll
        for (int i = 0; i < 4; i++){
            int idx = i*256 + tid;
            int row = idx >> 4, c = idx & 15;
            cpasync16(sb + so + row*256 + (((c ^ (row&7)))<<4),
                      g + (long)(k0+row)*ld + c0 + c*8);
        }
    };
    auto loadStage = [&](int s, int k0){
        uint32_t so = s * stageB;
        ldTile(Ah, lda, brow, k0, so);
        if (PASSES==3) ldTile(Al, lda, brow, k0, so + TILEB);
        uint32_t bo = so + (PASSES==3 ? 2 : 1) * TILEB;
        if (TRB){
            ldTileT(Bh, ldb, bcol, k0, bo);
            if (PASSES==3) ldTileT(Bl, ldb, bcol, k0, bo + TILEB);
        } else {
            ldTile(Bh, ldb, bcol, k0, bo);
            if (PASSES==3) ldTile(Bl, ldb, bcol, k0, bo + TILEB);
        }
        cp_commit();
    };

    // ---- per-thread ldmatrix address components ----
    uint32_t aRow[4], aS[4];
    const int akb = (lane >> 4) & 1;
    #pragma unroll
    for (int mq = 0; mq < 4; mq++){
        int r = wm0 + mq*16 + (lane & 15);
        aRow[mq] = r * 128; aS[mq] = r & 7;
    }
    uint32_t bRow[2], bS[2];
    const int bkb = (lane >> 3) & 1;
    #pragma unroll
    for (int nq = 0; nq < 2; nq++){
        int r = wn0 + nq*16 + (lane & 7) + ((lane & 16) ? 8 : 0);
        bRow[nq] = r * 128; bS[nq] = r & 7;
    }
    const int tKr = lane & 15;
    uint32_t tCk[2];
    #pragma unroll
    for (int nq = 0; nq < 2; nq++)
        tCk[nq] = (wn0 >> 3) + nq*2 + ((lane >> 4) & 1);

    float acc[4][4][4];
    #pragma unroll
    for (int a = 0; a < 4; a++)
        #pragma unroll
        for (int b = 0; b < 4; b++)
            #pragma unroll
            for (int c = 0; c < 4; c++) acc[a][b][c] = 0.f;

    auto compute = [&](int s){
        const uint32_t Ab  = sb + s*stageB;
        const uint32_t Alb = Ab + TILEB;
        const uint32_t Bb  = Ab + (PASSES==3 ? 2 : 1)*TILEB;
        const uint32_t Blb = Bb + TILEB;
        #pragma unroll
        for (int ks = 0; ks < 4; ks++){
            uint32_t ah[4][4], bh[8];
            #pragma unroll
            for (int mq = 0; mq < 4; mq++)
                ldsm4(ah[mq], Ab + aRow[mq] + ((uint32_t)((ks*2 + akb) ^ aS[mq]) << 4));
            if (TRB){
                const int kr = ks*16 + tKr;
                #pragma unroll
                for (int nq = 0; nq < 2; nq++)
                    ldsm4t(&bh[nq*4], Bb + kr*256 + ((tCk[nq] ^ (uint32_t)(kr & 7)) << 4));
            } else {
                #pragma unroll
                for (int nq = 0; nq < 2; nq++)
                    ldsm4(&bh[nq*4], Bb + bRow[nq] + ((uint32_t)((ks*2 + bkb) ^ bS[nq]) << 4));
            }
            #pragma unroll
            for (int mf = 0; mf < 4; mf++)
                #pragma unroll
                for (int nf = 0; nf < 4; nf++)
                    mma16816(acc[mf][nf], ah[mf], &bh[(nf>>1)*4 + (nf&1)*2]);

            if (PASSES == 3){
                uint32_t bl[8];
                if (TRB){
                    const int kr = ks*16 + tKr;
                    #pragma unroll
                    for (int nq = 0; nq < 2; nq++)
                        ldsm4t(&bl[nq*4], Blb + kr*256 + ((tCk[nq] ^ (uint32_t)(kr & 7)) << 4));
                } else {
                    #pragma unroll
                    for (int nq = 0; nq < 2; nq++)
                        ldsm4(&bl[nq*4], Blb + bRow[nq] + ((uint32_t)((ks*2 + bkb) ^ bS[nq]) << 4));
                }
                #pragma unroll
                for (int mf = 0; mf < 4; mf++)
                    #pragma unroll
                    for (int nf = 0; nf < 4; nf++)
                        mma16816(acc[mf][nf], ah[mf], &bl[(nf>>1)*4 + (nf&1)*2]);
                uint32_t al[4][4];
                #pragma unroll
                for (int mq = 0; mq < 4; mq++)
                    ldsm4(al[mq], Alb + aRow[mq] + ((uint32_t)((ks*2 + akb) ^ aS[mq]) << 4));
                #pragma unroll
                for (int mf = 0; mf < 4; mf++)
                    #pragma unroll
                    for (int nf = 0; nf < 4; nf++)
                        mma16816(acc[mf][nf], al[mf], &bh[(nf>>1)*4 + (nf&1)*2]);
            }
        }
    };

    // ---- pipelined mainloop (STAGES-deep) ----
    #pragma unroll
    for (int s = 0; s < STAGES-1; s++)
        if (s < NITER) loadStage(s, s*64);
    for (int it = 0; it < NITER; ++it){
        if (it == NITER-1) cp_wait<0>();
        else               cp_wait<STAGES-2>();
        __syncthreads();
        const int j = it + STAGES - 1;
        if (j < NITER) loadStage(j % STAGES, j*64);
        compute(it % STAGES);
    }

    // ---- epilogue ----
    #pragma unroll
    for (int mf = 0; mf < 4; mf++){
        const int r = brow + wm0 + mf*16 + (lane >> 2);
        #pragma unroll
        for (int nf = 0; nf < 4; nf++){
            const int c = bcol + wn0 + nf*8 + (lane & 3)*2;
            float v[4];
            #pragma unroll
            for (int q = 0; q < 4; q++) v[q] = alpha * acc[mf][nf][q];
            if (BIASF){
                const float b0 = __ldg(bias + c), b1 = __ldg(bias + c + 1);
                v[0] += b0; v[1] += b1; v[2] += b0; v[3] += b1;
            }
            if (RELUF){
                #pragma unroll
                for (int q = 0; q < 4; q++) v[q] = fmaxf(v[q], 0.f);
            }
            if (RESF){
                v[0] += __ldg(Res + (long)r*ldres + c);
                v[1] += __ldg(Res + (long)r*ldres + c + 1);
                v[2] += __ldg(Res + (long)(r+8)*ldres + c);
                v[3] += __ldg(Res + (long)(r+8)*ldres + c + 1);
            }
            #pragma unroll
            for (int half = 0; half < 2; half++){
                const long o = (long)(r + half*8) * ldc + c;
                const float x0 = v[half*2], x1 = v[half*2 + 1];
                if (OUTM == 1){
                    float2 f; f.x = x0; f.y = x1;
                    *reinterpret_cast<float2*>(Cf + o) = f;
                } else if (OUTM == 0){
                    __nv_bfloat162 p;
                    p.x = __float2bfloat16(x0); p.y = __float2bfloat16(x1);
                    *reinterpret_cast<__nv_bfloat162*>(Ch + o) = p;
                } else {
                    float2 f; f.x = x0; f.y = x1;
                    *reinterpret_cast<float2*>(Cf + o) = f;
                    bf16 h0,l0,h1,l1;
                    split2(x0,h0,l0); split2(x1,h1,l1);
                    __nv_bfloat162 ph, pl;
                    ph.x = h0; ph.y = h1; pl.x = l0; pl.y = l1;
                    *reinterpret_cast<__nv_bfloat162*>(Ch + o) = ph;
                    *reinterpret_cast<__nv_bfloat162*>(Cl + o) = pl;
                }
            }
        }
    }
}

// ---------------- register-resident causal softmax: S fp32 -> P bf16 ----------------
// One block (256 thr) per row; 8 elements per thread held in registers.
__global__ void __launch_bounds__(256)
softmax_reg(const float* __restrict__ S, bf16* __restrict__ P, int T)
{
    const int q = blockIdx.x;
    const long ro = ((long)blockIdx.y * T + q) * T;
    const int n = q + 1;
    const int tid = threadIdx.x;
    __shared__ float sh[8];
    const int lane = tid & 31, wid = tid >> 5;

    float v[8];
    #pragma unroll
    for (int i = 0; i < 8; i++){
        const int j = tid + i*256;
        v[i] = (j < n) ? __ldg(S + ro + j) : -INFINITY;
    }
    float m = v[0];
    #pragma unroll
    for (int i = 1; i < 8; i++) m = fmaxf(m, v[i]);
    #pragma unroll
    for (int o = 16; o > 0; o >>= 1) m = fmaxf(m, __shfl_xor_sync(0xffffffffu, m, o));
    if (lane == 0) sh[wid] = m;
    __syncthreads();
    m = sh[lane & 7];
    #pragma unroll
    for (int o = 4; o > 0; o >>= 1) m = fmaxf(m, __shfl_xor_sync(0xffffffffu, m, o));

    float s = 0.f;
    #pragma unroll
    for (int i = 0; i < 8; i++){ v[i] = __expf(v[i] - m); s += v[i]; }
    #pragma unroll
    for (int o = 16; o > 0; o >>= 1) s += __shfl_xor_sync(0xffffffffu, s, o);
    __syncthreads();
    if (lane == 0) sh[wid] = s;
    __syncthreads();
    s = sh[0]+sh[1]+sh[2]+sh[3]+sh[4]+sh[5]+sh[6]+sh[7];
    const float inv = 1.f / s;

    #pragma unroll
    for (int i = 0; i < 8; i += 2){
        const int j = tid + i*256;
        P[ro + j] = __float2bfloat16(v[i] * inv);
        P[ro + j + 256] = __float2bfloat16(v[i+1] * inv);
    }
}

// ---------------- host ----------------
#define GETB(sym, var) bf16* var; cudaGetSymbolAddress((void**)&var, sym)

extern "C" void kernel_launch(void* const* d_in, const int* in_sizes, int n_in,
                              void* d_out, int out_size)
{
    (void)in_sizes; (void)n_in; (void)out_size;
    const float* x  = (const float*)d_in[0];
    const float* Wq = (const float*)d_in[1];
    const float* Wk = (const float*)d_in[2];
    const float* Wv = (const float*)d_in[3];
    const float* Wu = (const float*)d_in[4];
    const float* bu = (const float*)d_in[5];
    const float* W1 = (const float*)d_in[6];
    const float* b1 = (const float*)d_in[7];
    const float* W2 = (const float*)d_in[8];
    const float* b2 = (const float*)d_in[9];
    float* out = (float*)d_out;

    GETB(g_Xb,Xb);
    GETB(g_Wqb,Wqb); GETB(g_Wkb,Wkb); GETB(g_Wvb,Wvb); GETB(g_Wub,Wub);
    GETB(g_W1h,W1h); GETB(g_W1l,W1l); GETB(g_W2h,W2h); GETB(g_W2l,W2l);
    GETB(g_Q,Q); GETB(g_K,Kb); GETB(g_V,V);
    GETB(g_P,P); GETB(g_O,O);
    GETB(g_X1h,X1h); GETB(g_X1l,X1l); GETB(g_Hh,Hh); GETB(g_Hl,Hl);
    float *S, *X1;
    cudaGetSymbolAddress((void**)&S,  g_S);
    cudaGetSymbolAddress((void**)&X1, g_X1);

    // instantiations
    auto gQKV = gmma<1,true ,0,false,false,false,false,false,3,3>; // fused QKV
    auto gS   = gmma<1,false,1,false,false,false,true ,false,1,3>; // QK^T -> fp32, causal skip
    auto gPV  = gmma<1,true ,0,false,false,false,false,true ,1,3>; // P@V, causal K bound
    auto gWu  = gmma<1,true ,2,true ,false,true ,false,false,1,3>; // O@Wu+bu+x -> fp32 + h/l
    auto gF1  = gmma<3,true ,0,true ,true ,false,false,false,1,2>; // relu(X1@W1+b1) 3-pass
    auto gF2  = gmma<3,true ,1,true ,false,true ,false,false,1,2>; // X1 + H@W2+b2 3-pass

    const int SM1 = 3*2*TILEB;   // 96 KB  (3-stage single-pass)
    const int SM3 = 2*4*TILEB;   // 128 KB (2-stage 3-pass)
    cudaFuncSetAttribute(gQKV, cudaFuncAttributeMaxDynamicSharedMemorySize, SM1);
    cudaFuncSetAttribute(gS  , cudaFuncAttributeMaxDynamicSharedMemorySize, SM1);
    cudaFuncSetAttribute(gPV , cudaFuncAttributeMaxDynamicSharedMemorySize, SM1);
    cudaFuncSetAttribute(gWu , cudaFuncAttributeMaxDynamicSharedMemorySize, SM1);
    cudaFuncSetAttribute(gF1 , cudaFuncAttributeMaxDynamicSharedMemorySize, SM3);
    cudaFuncSetAttribute(gF2 , cudaFuncAttributeMaxDynamicSharedMemorySize, SM3);

    // ---- 0. dtype conversions (2 launches) ----
    conv5<<<5*256, 256>>>(x, Xb, Wq, Wqb, Wk, Wkb, Wv, Wvb, Wu, Wub);
    conv_hl2<<<2*64, 256>>>(W1, W1h, W1l, W2, W2h, W2l);

    const long sTT = (long)TSEQ*TSEQ;

    // ---- 1. fused Q,K,V projections (z selects weight/output) ----
    gQKV<<<dim3(DPROJ/128, NTOK/128, 3), 256, SM1>>>(
        DK, 1.f, Xb, nullptr, DK, 0, 0,
        Wqb, nullptr, DPROJ, 0, 0, Wkb, Wvb,
        nullptr, Q, nullptr, Kb, V, DPROJ, 0, 0,
        nullptr, nullptr, 0, 1);

    // ---- 2. S = (1/32) Q K^T per (b,h), causal block skip ----
    gS<<<dim3(TSEQ/128, TSEQ/128, BSZ*HH), 256, SM1>>>(
        DK, 0.03125f,
        Q,  nullptr, DPROJ, (long)TSEQ*DPROJ, DK,
        Kb, nullptr, DPROJ, (long)TSEQ*DPROJ, DK,
        nullptr, nullptr,
        S, nullptr, nullptr, nullptr, nullptr, TSEQ, (long)HH*sTT, sTT,
        nullptr, nullptr, 0, HH);

    // ---- 3. softmax -> P bf16 (masked lanes produce exact 0) ----
    softmax_reg<<<dim3(TSEQ, BSZ*HH), 256>>>(S, P, TSEQ);

    // ---- 4. O = P @ V per (b,h), causal K bound ----
    gPV<<<dim3(DK/128, TSEQ/128, BSZ*HH), 256, SM1>>>(
        TSEQ, 1.f,
        P, nullptr, TSEQ, (long)HH*sTT, sTT,
        V, nullptr, DPROJ, (long)TSEQ*DPROJ, DK,
        nullptr, nullptr,
        nullptr, O, nullptr, nullptr, nullptr, DPROJ, (long)TSEQ*DPROJ, DK,
        nullptr, nullptr, 0, HH);

    // ---- 5. X1 = x + O@Wu + bu  (fp32 + hi/lo) ----
    gWu<<<dim3(DK/128, NTOK/128, 1), 256, SM1>>>(
        DPROJ, 1.f, O, nullptr, DPROJ, 0, 0,
        Wub, nullptr, DK, 0, 0, nullptr, nullptr,
        X1, X1h, X1l, nullptr, nullptr, DK, 0, 0, bu, x, DK, 1);

    // ---- 6. H = relu(X1@W1 + b1)  (3-pass) ----
    gF1<<<dim3(DK/128, NTOK/128, 1), 256, SM3>>>(
        DK, 1.f, X1h, X1l, DK, 0, 0,
        W1h, W1l, DK, 0, 0, nullptr, nullptr,
        nullptr, Hh, Hl, nullptr, nullptr, DK, 0, 0, b1, nullptr, 0, 1);

    // ---- 7. out = X1 + H@W2 + b2  (3-pass) ----
    gF2<<<dim3(DK/128, NTOK/128, 1), 256, SM3>>>(
        DK, 1.f, Hh, Hl, DK, 0, 0,
        W2h, W2l, DK, 0, 0, nullptr, nullptr,
        out, nullptr, nullptr, nullptr, nullptr, DK, 0, 0, b2, X1, DK, 1);
}

// round 6
// speedup vs baseline: 7.9686x; 1.0948x over previous
#include <cuda_runtime.h>
#include <cuda_bf16.h>
#include <stdint.h>
#include <math.h>

#define BSZ 2
#define TSEQ 2048
#define DK 1024
#define HH 4
#define NTOK (BSZ*TSEQ)      // 4096
#define DPROJ (HH*DK)        // 4096
typedef __nv_bfloat16 bf16;

// ---------------- scratch (device globals, allocation-free) ----------------
__device__ bf16 g_Xb [(size_t)NTOK*DK];
__device__ bf16 g_Wqb[(size_t)DK*DPROJ];
__device__ bf16 g_Wkb[(size_t)DK*DPROJ];
__device__ bf16 g_Wvb[(size_t)DK*DPROJ];
__device__ bf16 g_Wub[(size_t)DPROJ*DK];
__device__ bf16 g_W1h[(size_t)DK*DK], g_W1l[(size_t)DK*DK];
__device__ bf16 g_W2h[(size_t)DK*DK], g_W2l[(size_t)DK*DK];
__device__ bf16 g_Q[(size_t)NTOK*DPROJ];
__device__ bf16 g_K[(size_t)NTOK*DPROJ];
__device__ bf16 g_V[(size_t)NTOK*DPROJ];
__device__ float g_S[(size_t)BSZ*HH*TSEQ*TSEQ];
__device__ bf16  g_P[(size_t)BSZ*HH*TSEQ*TSEQ];
__device__ bf16 g_O[(size_t)NTOK*DPROJ];
__device__ float g_X1[(size_t)NTOK*DK];
__device__ bf16 g_X1h[(size_t)NTOK*DK], g_X1l[(size_t)NTOK*DK];
__device__ bf16 g_Hh[(size_t)NTOK*DK],  g_Hl[(size_t)NTOK*DK];

// ---------------- PTX helpers ----------------
static __device__ __forceinline__ uint32_t s2u(const void* p){
    uint32_t a;
    asm("{ .reg .u64 t; cvta.to.shared.u64 t, %1; cvt.u32.u64 %0, t; }" : "=r"(a) : "l"(p));
    return a;
}
static __device__ __forceinline__ void cpasync16(uint32_t dst, const void* src){
    asm volatile("cp.async.cg.shared.global [%0], [%1], 16;"
                 :: "r"(dst), "l"(__cvta_generic_to_global(src)) : "memory");
}
static __device__ __forceinline__ void cp_commit(){
    asm volatile("cp.async.commit_group;" ::: "memory");
}
template<int N>
static __device__ __forceinline__ void cp_wait(){
    asm volatile("cp.async.wait_group %0;" :: "n"(N) : "memory");
}
static __device__ __forceinline__ void ldsm4(uint32_t* r, uint32_t a){
    asm volatile("ldmatrix.sync.aligned.m8n8.x4.shared.b16 {%0,%1,%2,%3}, [%4];"
                 : "=r"(r[0]),"=r"(r[1]),"=r"(r[2]),"=r"(r[3]) : "r"(a));
}
static __device__ __forceinline__ void ldsm4t(uint32_t* r, uint32_t a){
    asm volatile("ldmatrix.sync.aligned.m8n8.x4.trans.shared.b16 {%0,%1,%2,%3}, [%4];"
                 : "=r"(r[0]),"=r"(r[1]),"=r"(r[2]),"=r"(r[3]) : "r"(a));
}
static __device__ __forceinline__ void mma16816(float* c, const uint32_t* a, const uint32_t* b){
    asm volatile(
        "mma.sync.aligned.m16n8k16.row.col.f32.bf16.bf16.f32 "
        "{%0,%1,%2,%3}, {%4,%5,%6,%7}, {%8,%9}, {%0,%1,%2,%3};"
        : "+f"(c[0]),"+f"(c[1]),"+f"(c[2]),"+f"(c[3])
        : "r"(a[0]),"r"(a[1]),"r"(a[2]),"r"(a[3]), "r"(b[0]),"r"(b[1]));
}
static __device__ __forceinline__ void split2(float v, bf16& h, bf16& l){
    h = __float2bfloat16(v);
    l = __float2bfloat16(v - __bfloat162float(h));
}

// ---------------- fused conversion kernels ----------------
__global__ void __launch_bounds__(256)
conv5(const float* __restrict__ s0, bf16* __restrict__ d0,
      const float* __restrict__ s1, bf16* __restrict__ d1,
      const float* __restrict__ s2, bf16* __restrict__ d2,
      const float* __restrict__ s3, bf16* __restrict__ d3,
      const float* __restrict__ s4, bf16* __restrict__ d4)
{
    const int seg = blockIdx.x >> 8, b = blockIdx.x & 255;
    const float* s; bf16* d;
    switch (seg){
        case 0: s = s0; d = d0; break;
        case 1: s = s1; d = d1; break;
        case 2: s = s2; d = d2; break;
        case 3: s = s3; d = d3; break;
        default: s = s4; d = d4; break;
    }
    const int base = b * (256*16);
    #pragma unroll 4
    for (int i = 0; i < 16; i++){
        int idx = base + i*256 + threadIdx.x;
        float4 v = reinterpret_cast<const float4*>(s)[idx];
        __nv_bfloat162 a, c;
        a.x = __float2bfloat16(v.x); a.y = __float2bfloat16(v.y);
        c.x = __float2bfloat16(v.z); c.y = __float2bfloat16(v.w);
        reinterpret_cast<__nv_bfloat162*>(d)[2*idx]   = a;
        reinterpret_cast<__nv_bfloat162*>(d)[2*idx+1] = c;
    }
}
__global__ void __launch_bounds__(256)
conv_hl2(const float* __restrict__ s0, bf16* __restrict__ h0, bf16* __restrict__ l0,
         const float* __restrict__ s1, bf16* __restrict__ h1, bf16* __restrict__ l1)
{
    const int seg = blockIdx.x >> 6, b = blockIdx.x & 63;
    const float* s = seg ? s1 : s0;
    bf16* dh = seg ? h1 : h0;
    bf16* dl = seg ? l1 : l0;
    const int base = b * (256*16);
    #pragma unroll 4
    for (int i = 0; i < 16; i++){
        int idx = base + i*256 + threadIdx.x;
        float4 v = reinterpret_cast<const float4*>(s)[idx];
        bf16 a0,a1,a2,a3,c0,c1,c2,c3;
        split2(v.x,a0,c0); split2(v.y,a1,c1); split2(v.z,a2,c2); split2(v.w,a3,c3);
        __nv_bfloat162 ha, hb, la, lb;
        ha.x=a0; ha.y=a1; hb.x=a2; hb.y=a3;
        la.x=c0; la.y=c1; lb.x=c2; lb.y=c3;
        reinterpret_cast<__nv_bfloat162*>(dh)[2*idx]   = ha;
        reinterpret_cast<__nv_bfloat162*>(dh)[2*idx+1] = hb;
        reinterpret_cast<__nv_bfloat162*>(dl)[2*idx]   = la;
        reinterpret_cast<__nv_bfloat162*>(dl)[2*idx+1] = lb;
    }
}

// ---------------- mma.sync GEMM ----------------
// C = alpha * (A)(B) (+bias)(relu)(+res)
// A: [M,K] bf16 row-major.
// TRB=false: B given as [N,K] row-major (NT). TRB=true: B given as [K,N] row-major.
// PASSES=3: hi/lo emulation. OUTM: 0 bf16; 1 fp32; 2 fp32+hi/lo.
// CSKIP: triangular-block launch (grid.x = nb*(nb+1)/2, decode x<=y).
// CK: causal K bound. NSEL=3: fused QKV. STAGES: cp.async depth. MINB: min blocks/SM.
#define TILEB 16384

template<int PASSES, bool TRB, int OUTM, bool BIASF, bool RELUF, bool RESF,
         bool CSKIP, bool CK, int NSEL, int STAGES, int MINB>
__global__ void __launch_bounds__(256, MINB)
gmma(int Kdim, float alpha,
     const bf16* __restrict__ Ah, const bf16* __restrict__ Al, int lda, long sAo, long sAi,
     const bf16* __restrict__ Bh, const bf16* __restrict__ Bl, int ldb, long sBo, long sBi,
     const bf16* __restrict__ Bh2, const bf16* __restrict__ Bh3,
     float* __restrict__ Cf, bf16* __restrict__ Ch, bf16* __restrict__ Cl,
     bf16* __restrict__ Ch2, bf16* __restrict__ Ch3,
     int ldc, long sCo, long sCi,
     const float* __restrict__ bias, const float* __restrict__ Res, int ldres,
     int innerCount)
{
    extern __shared__ char smem[];
    const uint32_t sb = s2u(smem);
    const int tid = threadIdx.x, wid = tid >> 5, lane = tid & 31;
    const int wm0 = (wid >> 2) * 64;
    const int wn0 = (wid & 3) * 32;

    // block coords (triangular decode when CSKIP)
    int bxi, byi;
    if (CSKIP){
        const int i = blockIdx.x;
        int y = (int)((sqrtf(8.f*(float)i + 1.f) - 1.f) * 0.5f);
        while ((y+1)*(y+2)/2 <= i) y++;
        while (y*(y+1)/2 > i) y--;
        byi = y; bxi = i - y*(y+1)/2;
    } else {
        bxi = blockIdx.x; byi = blockIdx.y;
    }

    if (NSEL == 3){
        const int sel = blockIdx.z;
        if (sel == 1){ Bh = Bh2; Ch = Ch2; }
        else if (sel == 2){ Bh = Bh3; Ch = Ch3; }
    } else {
        const int z = blockIdx.z, zo = z / innerCount, zi = z - zo * innerCount;
        Ah += zo*sAo + (long)zi*sAi;  if (PASSES==3) Al += zo*sAo + (long)zi*sAi;
        Bh += zo*sBo + (long)zi*sBi;  if (PASSES==3) Bl += zo*sBo + (long)zi*sBi;
        const long coff = zo*sCo + (long)zi*sCi;
        if (Cf) Cf += coff;
        if (Ch) Ch += coff;
        if (Cl) Cl += coff;
    }

    const int brow = byi * 128, bcol = bxi * 128;
    const int kEnd = CK ? (byi + 1) * 128 : Kdim;
    const int NITER = kEnd >> 6;

    const uint32_t stageB = (PASSES==3 ? 4 : 2) * TILEB;

    // ---- loaders ----
    auto ldTile = [&](const bf16* g, int ld, int r0, int k0, uint32_t so){
        #pragma unroll
        for (int i = 0; i < 4; i++){
            int idx = i*256 + tid;
            int row = idx >> 3, c = idx & 7;
            cpasync16(sb + so + row*128 + (((c ^ (row&7)))<<4),
                      g + (long)(r0+row)*ld + k0 + c*8);
        }
    };
    auto ldTileT = [&](const bf16* g, int ld, int c0, int k0, uint32_t so){
        #pragma unroll
        for (int i = 0; i < 4; i++){
            int idx = i*256 + tid;
            int row = idx >> 4, c = idx & 15;
            cpasync16(sb + so + row*256 + (((c ^ (row&7)))<<4),
                      g + (long)(k0+row)*ld + c0 + c*8);
        }
    };
    auto loadStage = [&](int s, int k0){
        uint32_t so = s * stageB;
        ldTile(Ah, lda, brow, k0, so);
        if (PASSES==3) ldTile(Al, lda, brow, k0, so + TILEB);
        uint32_t bo = so + (PASSES==3 ? 2 : 1) * TILEB;
        if (TRB){
            ldTileT(Bh, ldb, bcol, k0, bo);
            if (PASSES==3) ldTileT(Bl, ldb, bcol, k0, bo + TILEB);
        } else {
            ldTile(Bh, ldb, bcol, k0, bo);
            if (PASSES==3) ldTile(Bl, ldb, bcol, k0, bo + TILEB);
        }
        cp_commit();
    };

    // ---- per-thread ldmatrix address components ----
    uint32_t aRow[4], aS[4];
    const int akb = (lane >> 4) & 1;
    #pragma unroll
    for (int mq = 0; mq < 4; mq++){
        int r = wm0 + mq*16 + (lane & 15);
        aRow[mq] = r * 128; aS[mq] = r & 7;
    }
    uint32_t bRow[2], bS[2];
    const int bkb = (lane >> 3) & 1;
    #pragma unroll
    for (int nq = 0; nq < 2; nq++){
        int r = wn0 + nq*16 + (lane & 7) + ((lane & 16) ? 8 : 0);
        bRow[nq] = r * 128; bS[nq] = r & 7;
    }
    const int tKr = lane & 15;
    uint32_t tCk[2];
    #pragma unroll
    for (int nq = 0; nq < 2; nq++)
        tCk[nq] = (wn0 >> 3) + nq*2 + ((lane >> 4) & 1);

    float acc[4][4][4];
    #pragma unroll
    for (int a = 0; a < 4; a++)
        #pragma unroll
        for (int b = 0; b < 4; b++)
            #pragma unroll
            for (int c = 0; c < 4; c++) acc[a][b][c] = 0.f;

    auto compute = [&](int s){
        const uint32_t Ab  = sb + s*stageB;
        const uint32_t Alb = Ab + TILEB;
        const uint32_t Bb  = Ab + (PASSES==3 ? 2 : 1)*TILEB;
        const uint32_t Blb = Bb + TILEB;
        #pragma unroll
        for (int ks = 0; ks < 4; ks++){
            uint32_t ah[4][4], bh[8];
            #pragma unroll
            for (int mq = 0; mq < 4; mq++)
                ldsm4(ah[mq], Ab + aRow[mq] + ((uint32_t)((ks*2 + akb) ^ aS[mq]) << 4));
            if (TRB){
                const int kr = ks*16 + tKr;
                #pragma unroll
                for (int nq = 0; nq < 2; nq++)
                    ldsm4t(&bh[nq*4], Bb + kr*256 + ((tCk[nq] ^ (uint32_t)(kr & 7)) << 4));
            } else {
                #pragma unroll
                for (int nq = 0; nq < 2; nq++)
                    ldsm4(&bh[nq*4], Bb + bRow[nq] + ((uint32_t)((ks*2 + bkb) ^ bS[nq]) << 4));
            }
            #pragma unroll
            for (int mf = 0; mf < 4; mf++)
                #pragma unroll
                for (int nf = 0; nf < 4; nf++)
                    mma16816(acc[mf][nf], ah[mf], &bh[(nf>>1)*4 + (nf&1)*2]);

            if (PASSES == 3){
                uint32_t bl[8];
                if (TRB){
                    const int kr = ks*16 + tKr;
                    #pragma unroll
                    for (int nq = 0; nq < 2; nq++)
                        ldsm4t(&bl[nq*4], Blb + kr*256 + ((tCk[nq] ^ (uint32_t)(kr & 7)) << 4));
                } else {
                    #pragma unroll
                    for (int nq = 0; nq < 2; nq++)
                        ldsm4(&bl[nq*4], Blb + bRow[nq] + ((uint32_t)((ks*2 + bkb) ^ bS[nq]) << 4));
                }
                #pragma unroll
                for (int mf = 0; mf < 4; mf++)
                    #pragma unroll
                    for (int nf = 0; nf < 4; nf++)
                        mma16816(acc[mf][nf], ah[mf], &bl[(nf>>1)*4 + (nf&1)*2]);
                uint32_t al[4][4];
                #pragma unroll
                for (int mq = 0; mq < 4; mq++)
                    ldsm4(al[mq], Alb + aRow[mq] + ((uint32_t)((ks*2 + akb) ^ aS[mq]) << 4));
                #pragma unroll
                for (int mf = 0; mf < 4; mf++)
                    #pragma unroll
                    for (int nf = 0; nf < 4; nf++)
                        mma16816(acc[mf][nf], al[mf], &bh[(nf>>1)*4 + (nf&1)*2]);
            }
        }
    };

    // ---- pipelined mainloop (STAGES-deep) ----
    #pragma unroll
    for (int s = 0; s < STAGES-1; s++)
        if (s < NITER) loadStage(s, s*64);
    for (int it = 0; it < NITER; ++it){
        if (it == NITER-1) cp_wait<0>();
        else               cp_wait<STAGES-2>();
        __syncthreads();
        const int j = it + STAGES - 1;
        if (j < NITER) loadStage(j % STAGES, j*64);
        compute(it % STAGES);
    }

    // ---- epilogue ----
    #pragma unroll
    for (int mf = 0; mf < 4; mf++){
        const int r = brow + wm0 + mf*16 + (lane >> 2);
        #pragma unroll
        for (int nf = 0; nf < 4; nf++){
            const int c = bcol + wn0 + nf*8 + (lane & 3)*2;
            float v[4];
            #pragma unroll
            for (int q = 0; q < 4; q++) v[q] = alpha * acc[mf][nf][q];
            if (BIASF){
                const float b0 = __ldg(bias + c), b1 = __ldg(bias + c + 1);
                v[0] += b0; v[1] += b1; v[2] += b0; v[3] += b1;
            }
            if (RELUF){
                #pragma unroll
                for (int q = 0; q < 4; q++) v[q] = fmaxf(v[q], 0.f);
            }
            if (RESF){
                v[0] += __ldg(Res + (long)r*ldres + c);
                v[1] += __ldg(Res + (long)r*ldres + c + 1);
                v[2] += __ldg(Res + (long)(r+8)*ldres + c);
                v[3] += __ldg(Res + (long)(r+8)*ldres + c + 1);
            }
            #pragma unroll
            for (int half = 0; half < 2; half++){
                const long o = (long)(r + half*8) * ldc + c;
                const float x0 = v[half*2], x1 = v[half*2 + 1];
                if (OUTM == 1){
                    float2 f; f.x = x0; f.y = x1;
                    *reinterpret_cast<float2*>(Cf + o) = f;
                } else if (OUTM == 0){
                    __nv_bfloat162 p;
                    p.x = __float2bfloat16(x0); p.y = __float2bfloat16(x1);
                    *reinterpret_cast<__nv_bfloat162*>(Ch + o) = p;
                } else {
                    float2 f; f.x = x0; f.y = x1;
                    *reinterpret_cast<float2*>(Cf + o) = f;
                    bf16 h0,l0,h1,l1;
                    split2(x0,h0,l0); split2(x1,h1,l1);
                    __nv_bfloat162 ph, pl;
                    ph.x = h0; ph.y = h1; pl.x = l0; pl.y = l1;
                    *reinterpret_cast<__nv_bfloat162*>(Ch + o) = ph;
                    *reinterpret_cast<__nv_bfloat162*>(Cl + o) = pl;
                }
            }
        }
    }
}

// ---------------- register-resident causal softmax ----------------
__global__ void __launch_bounds__(256)
softmax_reg(const float* __restrict__ S, bf16* __restrict__ P, int T)
{
    const int q = blockIdx.x;
    const long ro = ((long)blockIdx.y * T + q) * T;
    const int n = q + 1;
    const int tid = threadIdx.x;
    __shared__ float sh[8];
    const int lane = tid & 31, wid = tid >> 5;

    float v[8];
    #pragma unroll
    for (int i = 0; i < 8; i++){
        const int j = tid + i*256;
        v[i] = (j < n) ? __ldg(S + ro + j) : -INFINITY;
    }
    float m = v[0];
    #pragma unroll
    for (int i = 1; i < 8; i++) m = fmaxf(m, v[i]);
    #pragma unroll
    for (int o = 16; o > 0; o >>= 1) m = fmaxf(m, __shfl_xor_sync(0xffffffffu, m, o));
    if (lane == 0) sh[wid] = m;
    __syncthreads();
    m = sh[lane & 7];
    #pragma unroll
    for (int o = 4; o > 0; o >>= 1) m = fmaxf(m, __shfl_xor_sync(0xffffffffu, m, o));

    float s = 0.f;
    #pragma unroll
    for (int i = 0; i < 8; i++){ v[i] = __expf(v[i] - m); s += v[i]; }
    #pragma unroll
    for (int o = 16; o > 0; o >>= 1) s += __shfl_xor_sync(0xffffffffu, s, o);
    __syncthreads();
    if (lane == 0) sh[wid] = s;
    __syncthreads();
    s = sh[0]+sh[1]+sh[2]+sh[3]+sh[4]+sh[5]+sh[6]+sh[7];
    const float inv = 1.f / s;

    #pragma unroll
    for (int i = 0; i < 8; i += 2){
        const int j = tid + i*256;
        P[ro + j] = __float2bfloat16(v[i] * inv);
        P[ro + j + 256] = __float2bfloat16(v[i+1] * inv);
    }
}

// ---------------- host ----------------
#define GETB(sym, var) bf16* var; cudaGetSymbolAddress((void**)&var, sym)

extern "C" void kernel_launch(void* const* d_in, const int* in_sizes, int n_in,
                              void* d_out, int out_size)
{
    (void)in_sizes; (void)n_in; (void)out_size;
    const float* x  = (const float*)d_in[0];
    const float* Wq = (const float*)d_in[1];
    const float* Wk = (const float*)d_in[2];
    const float* Wv = (const float*)d_in[3];
    const float* Wu = (const float*)d_in[4];
    const float* bu = (const float*)d_in[5];
    const float* W1 = (const float*)d_in[6];
    const float* b1 = (const float*)d_in[7];
    const float* W2 = (const float*)d_in[8];
    const float* b2 = (const float*)d_in[9];
    float* out = (float*)d_out;

    GETB(g_Xb,Xb);
    GETB(g_Wqb,Wqb); GETB(g_Wkb,Wkb); GETB(g_Wvb,Wvb); GETB(g_Wub,Wub);
    GETB(g_W1h,W1h); GETB(g_W1l,W1l); GETB(g_W2h,W2h); GETB(g_W2l,W2l);
    GETB(g_Q,Q); GETB(g_K,Kb); GETB(g_V,V);
    GETB(g_P,P); GETB(g_O,O);
    GETB(g_X1h,X1h); GETB(g_X1l,X1l); GETB(g_Hh,Hh); GETB(g_Hl,Hl);
    float *S, *X1;
    cudaGetSymbolAddress((void**)&S,  g_S);
    cudaGetSymbolAddress((void**)&X1, g_X1);

    // instantiations (single-pass: 2 CTAs/SM; 3-pass: 1 CTA/SM)
    auto gQKV = gmma<1,true ,0,false,false,false,false,false,3,3,2>;
    auto gS   = gmma<1,false,1,false,false,false,true ,false,1,3,2>;
    auto gPV  = gmma<1,true ,0,false,false,false,false,true ,1,3,2>;
    auto gWu  = gmma<1,true ,2,true ,false,true ,false,false,1,3,2>;
    auto gF1  = gmma<3,true ,0,true ,true ,false,false,false,1,2,1>;
    auto gF2  = gmma<3,true ,1,true ,false,true ,false,false,1,2,1>;

    const int SM1 = 3*2*TILEB;   // 96 KB
    const int SM3 = 2*4*TILEB;   // 128 KB
    cudaFuncSetAttribute(gQKV, cudaFuncAttributeMaxDynamicSharedMemorySize, SM1);
    cudaFuncSetAttribute(gS  , cudaFuncAttributeMaxDynamicSharedMemorySize, SM1);
    cudaFuncSetAttribute(gPV , cudaFuncAttributeMaxDynamicSharedMemorySize, SM1);
    cudaFuncSetAttribute(gWu , cudaFuncAttributeMaxDynamicSharedMemorySize, SM1);
    cudaFuncSetAttribute(gF1 , cudaFuncAttributeMaxDynamicSharedMemorySize, SM3);
    cudaFuncSetAttribute(gF2 , cudaFuncAttributeMaxDynamicSharedMemorySize, SM3);

    // ---- 0. dtype conversions ----
    conv5<<<5*256, 256>>>(x, Xb, Wq, Wqb, Wk, Wkb, Wv, Wvb, Wu, Wub);
    conv_hl2<<<2*64, 256>>>(W1, W1h, W1l, W2, W2h, W2l);

    const long sTT = (long)TSEQ*TSEQ;

    // ---- 1. fused Q,K,V projections ----
    gQKV<<<dim3(DPROJ/128, NTOK/128, 3), 256, SM1>>>(
        DK, 1.f, Xb, nullptr, DK, 0, 0,
        Wqb, nullptr, DPROJ, 0, 0, Wkb, Wvb,
        nullptr, Q, nullptr, Kb, V, DPROJ, 0, 0,
        nullptr, nullptr, 0, 1);

    // ---- 2. S = (1/32) Q K^T, triangular block launch ----
    {
        const int nb = TSEQ/128;                 // 16
        gS<<<dim3(nb*(nb+1)/2, 1, BSZ*HH), 256, SM1>>>(
            DK, 0.03125f,
            Q,  nullptr, DPROJ, (long)TSEQ*DPROJ, DK,
            Kb, nullptr, DPROJ, (long)TSEQ*DPROJ, DK,
            nullptr, nullptr,
            S, nullptr, nullptr, nullptr, nullptr, TSEQ, (long)HH*sTT, sTT,
            nullptr, nullptr, 0, HH);
    }

    // ---- 3. softmax -> P bf16 ----
    softmax_reg<<<dim3(TSEQ, BSZ*HH), 256>>>(S, P, TSEQ);

    // ---- 4. O = P @ V, causal K bound ----
    gPV<<<dim3(DK/128, TSEQ/128, BSZ*HH), 256, SM1>>>(
        TSEQ, 1.f,
        P, nullptr, TSEQ, (long)HH*sTT, sTT,
        V, nullptr, DPROJ, (long)TSEQ*DPROJ, DK,
        nullptr, nullptr,
        nullptr, O, nullptr, nullptr, nullptr, DPROJ, (long)TSEQ*DPROJ, DK,
        nullptr, nullptr, 0, HH);

    // ---- 5. X1 = x + O@Wu + bu ----
    gWu<<<dim3(DK/128, NTOK/128, 1), 256, SM1>>>(
        DPROJ, 1.f, O, nullptr, DPROJ, 0, 0,
        Wub, nullptr, DK, 0, 0, nullptr, nullptr,
        X1, X1h, X1l, nullptr, nullptr, DK, 0, 0, bu, x, DK, 1);

    // ---- 6. H = relu(X1@W1 + b1)  (3-pass) ----
    gF1<<<dim3(DK/128, NTOK/128, 1), 256, SM3>>>(
        DK, 1.f, X1h, X1l, DK, 0, 0,
        W1h, W1l, DK, 0, 0, nullptr, nullptr,
        nullptr, Hh, Hl, nullptr, nullptr, DK, 0, 0, b1, nullptr, 0, 1);

    // ---- 7. out = X1 + H@W2 + b2  (3-pass) ----
    gF2<<<dim3(DK/128, NTOK/128, 1), 256, SM3>>>(
        DK, 1.f, Hh, Hl, DK, 0, 0,
        W2h, W2l, DK, 0, 0, nullptr, nullptr,
        out, nullptr, nullptr, nullptr, nullptr, DK, 0, 0, b2, X1, DK, 1);
}

// round 7
// speedup vs baseline: 8.3364x; 1.0462x over previous
#include <cuda_runtime.h>
#include <cuda_bf16.h>
#include <stdint.h>
#include <math.h>

#define BSZ 2
#define TSEQ 2048
#define DK 1024
#define HH 4
#define NTOK (BSZ*TSEQ)      // 4096
#define DPROJ (HH*DK)        // 4096
typedef __nv_bfloat16 bf16;

// ---------------- scratch ----------------
__device__ bf16 g_Xb [(size_t)NTOK*DK];
__device__ bf16 g_Wqb[(size_t)DK*DPROJ];
__device__ bf16 g_Wkb[(size_t)DK*DPROJ];
__device__ bf16 g_Wvb[(size_t)DK*DPROJ];
__device__ bf16 g_Wub[(size_t)DPROJ*DK];
__device__ bf16 g_W1h[(size_t)DK*DK], g_W1l[(size_t)DK*DK];
__device__ bf16 g_W2h[(size_t)DK*DK], g_W2l[(size_t)DK*DK];
__device__ bf16 g_Q[(size_t)NTOK*DPROJ];
__device__ bf16 g_K[(size_t)NTOK*DPROJ];
__device__ bf16 g_V[(size_t)NTOK*DPROJ];
__device__ float g_S[(size_t)BSZ*HH*TSEQ*TSEQ];
__device__ bf16  g_P[(size_t)BSZ*HH*TSEQ*TSEQ];
__device__ bf16 g_O[(size_t)NTOK*DPROJ];
__device__ float g_X1[(size_t)NTOK*DK];
__device__ bf16 g_X1h[(size_t)NTOK*DK], g_X1l[(size_t)NTOK*DK];
__device__ bf16 g_Hh[(size_t)NTOK*DK],  g_Hl[(size_t)NTOK*DK];

// ---------------- PTX helpers ----------------
static __device__ __forceinline__ uint32_t s2u(const void* p){
    uint32_t a;
    asm("{ .reg .u64 t; cvta.to.shared.u64 t, %1; cvt.u32.u64 %0, t; }" : "=r"(a) : "l"(p));
    return a;
}
static __device__ __forceinline__ void cpasync16(uint32_t dst, const void* src){
    asm volatile("cp.async.cg.shared.global [%0], [%1], 16;"
                 :: "r"(dst), "l"(__cvta_generic_to_global(src)) : "memory");
}
static __device__ __forceinline__ void cp_commit(){
    asm volatile("cp.async.commit_group;" ::: "memory");
}
template<int N>
static __device__ __forceinline__ void cp_wait(){
    asm volatile("cp.async.wait_group %0;" :: "n"(N) : "memory");
}
static __device__ __forceinline__ void ldsm4(uint32_t* r, uint32_t a){
    asm volatile("ldmatrix.sync.aligned.m8n8.x4.shared.b16 {%0,%1,%2,%3}, [%4];"
                 : "=r"(r[0]),"=r"(r[1]),"=r"(r[2]),"=r"(r[3]) : "r"(a));
}
static __device__ __forceinline__ void ldsm4t(uint32_t* r, uint32_t a){
    asm volatile("ldmatrix.sync.aligned.m8n8.x4.trans.shared.b16 {%0,%1,%2,%3}, [%4];"
                 : "=r"(r[0]),"=r"(r[1]),"=r"(r[2]),"=r"(r[3]) : "r"(a));
}
static __device__ __forceinline__ void mma16816(float* c, const uint32_t* a, const uint32_t* b){
    asm volatile(
        "mma.sync.aligned.m16n8k16.row.col.f32.bf16.bf16.f32 "
        "{%0,%1,%2,%3}, {%4,%5,%6,%7}, {%8,%9}, {%0,%1,%2,%3};"
        : "+f"(c[0]),"+f"(c[1]),"+f"(c[2]),"+f"(c[3])
        : "r"(a[0]),"r"(a[1]),"r"(a[2]),"r"(a[3]), "r"(b[0]),"r"(b[1]));
}
static __device__ __forceinline__ void split2(float v, bf16& h, bf16& l){
    h = __float2bfloat16(v);
    l = __float2bfloat16(v - __bfloat162float(h));
}

// ---------------- fused conversion kernels ----------------
__global__ void __launch_bounds__(256)
conv5(const float* __restrict__ s0, bf16* __restrict__ d0,
      const float* __restrict__ s1, bf16* __restrict__ d1,
      const float* __restrict__ s2, bf16* __restrict__ d2,
      const float* __restrict__ s3, bf16* __restrict__ d3,
      const float* __restrict__ s4, bf16* __restrict__ d4)
{
    const int seg = blockIdx.x >> 8, b = blockIdx.x & 255;
    const float* s; bf16* d;
    switch (seg){
        case 0: s = s0; d = d0; break;
        case 1: s = s1; d = d1; break;
        case 2: s = s2; d = d2; break;
        case 3: s = s3; d = d3; break;
        default: s = s4; d = d4; break;
    }
    const int base = b * (256*16);
    #pragma unroll 4
    for (int i = 0; i < 16; i++){
        int idx = base + i*256 + threadIdx.x;
        float4 v = reinterpret_cast<const float4*>(s)[idx];
        __nv_bfloat162 a, c;
        a.x = __float2bfloat16(v.x); a.y = __float2bfloat16(v.y);
        c.x = __float2bfloat16(v.z); c.y = __float2bfloat16(v.w);
        reinterpret_cast<__nv_bfloat162*>(d)[2*idx]   = a;
        reinterpret_cast<__nv_bfloat162*>(d)[2*idx+1] = c;
    }
}
__global__ void __launch_bounds__(256)
conv_hl2(const float* __restrict__ s0, bf16* __restrict__ h0, bf16* __restrict__ l0,
         const float* __restrict__ s1, bf16* __restrict__ h1, bf16* __restrict__ l1)
{
    const int seg = blockIdx.x >> 6, b = blockIdx.x & 63;
    const float* s = seg ? s1 : s0;
    bf16* dh = seg ? h1 : h0;
    bf16* dl = seg ? l1 : l0;
    const int base = b * (256*16);
    #pragma unroll 4
    for (int i = 0; i < 16; i++){
        int idx = base + i*256 + threadIdx.x;
        float4 v = reinterpret_cast<const float4*>(s)[idx];
        bf16 a0,a1,a2,a3,c0,c1,c2,c3;
        split2(v.x,a0,c0); split2(v.y,a1,c1); split2(v.z,a2,c2); split2(v.w,a3,c3);
        __nv_bfloat162 ha, hb, la, lb;
        ha.x=a0; ha.y=a1; hb.x=a2; hb.y=a3;
        la.x=c0; la.y=c1; lb.x=c2; lb.y=c3;
        reinterpret_cast<__nv_bfloat162*>(dh)[2*idx]   = ha;
        reinterpret_cast<__nv_bfloat162*>(dh)[2*idx+1] = hb;
        reinterpret_cast<__nv_bfloat162*>(dl)[2*idx]   = la;
        reinterpret_cast<__nv_bfloat162*>(dl)[2*idx+1] = lb;
    }
}

// ================= single-pass GEMM, 64x64 warp tile, 128 threads ==============
// CTA tile 128x128, warps 2x2 (each 64x64), 3-stage cp.async, 2 CTAs/SM.
#define TILEB 16384   // 128x64 bf16 (or 64x128 for TRB)

template<bool TRB, int OUTM, bool BIASF, bool RELUF, bool RESF,
         bool CSKIP, bool CK, int NSEL>
__global__ void __launch_bounds__(128, 2)
gmma64(int Kdim, float alpha,
       const bf16* __restrict__ Ah, int lda, long sAo, long sAi,
       const bf16* __restrict__ Bh, int ldb, long sBo, long sBi,
       const bf16* __restrict__ Bh2, const bf16* __restrict__ Bh3,
       float* __restrict__ Cf, bf16* __restrict__ Ch, bf16* __restrict__ Cl,
       bf16* __restrict__ Ch2, bf16* __restrict__ Ch3,
       int ldc, long sCo, long sCi,
       const float* __restrict__ bias, const float* __restrict__ Res, int ldres,
       int innerCount)
{
    extern __shared__ char smem[];
    const uint32_t sb = s2u(smem);
    const int tid = threadIdx.x, wid = tid >> 5, lane = tid & 31;
    const int wm0 = (wid >> 1) * 64;     // warp row offset
    const int wn0 = (wid & 1) * 64;      // warp col offset

    int bxi, byi;
    if (CSKIP){
        const int i = blockIdx.x;
        int y = (int)((sqrtf(8.f*(float)i + 1.f) - 1.f) * 0.5f);
        while ((y+1)*(y+2)/2 <= i) y++;
        while (y*(y+1)/2 > i) y--;
        byi = y; bxi = i - y*(y+1)/2;
    } else {
        bxi = blockIdx.x; byi = blockIdx.y;
    }

    if (NSEL == 3){
        const int sel = blockIdx.z;
        if (sel == 1){ Bh = Bh2; Ch = Ch2; }
        else if (sel == 2){ Bh = Bh3; Ch = Ch3; }
    } else {
        const int z = blockIdx.z, zo = z / innerCount, zi = z - zo * innerCount;
        Ah += zo*sAo + (long)zi*sAi;
        Bh += zo*sBo + (long)zi*sBi;
        const long coff = zo*sCo + (long)zi*sCi;
        if (Cf) Cf += coff;
        if (Ch) Ch += coff;
        if (Cl) Cl += coff;
    }

    const int brow = byi * 128, bcol = bxi * 128;
    const int kEnd = CK ? (byi + 1) * 128 : Kdim;
    const int NITER = kEnd >> 6;
    const uint32_t stageB = 2 * TILEB;   // A tile + B tile

    // ---- loaders (128 threads, 8 chunks of 16B each) ----
    auto ldTile = [&](const bf16* g, int ld, int r0, int k0, uint32_t so){
        #pragma unroll
        for (int i = 0; i < 8; i++){
            int idx = i*128 + tid;
            int row = idx >> 3, c = idx & 7;
            cpasync16(sb + so + row*128 + (((c ^ (row&7)))<<4),
                      g + (long)(r0+row)*ld + k0 + c*8);
        }
    };
    auto ldTileT = [&](const bf16* g, int ld, int c0, int k0, uint32_t so){
        #pragma unroll
        for (int i = 0; i < 8; i++){
            int idx = i*128 + tid;
            int row = idx >> 4, c = idx & 15;
            cpasync16(sb + so + row*256 + (((c ^ (row&7)))<<4),
                      g + (long)(k0+row)*ld + c0 + c*8);
        }
    };
    auto loadStage = [&](int s, int k0){
        uint32_t so = s * stageB;
        ldTile(Ah, lda, brow, k0, so);
        if (TRB) ldTileT(Bh, ldb, bcol, k0, so + TILEB);
        else     ldTile (Bh, ldb, bcol, k0, so + TILEB);
        cp_commit();
    };

    // ---- fragment addressing ----
    uint32_t aRow[4], aS[4];
    const int akb = (lane >> 4) & 1;
    #pragma unroll
    for (int mq = 0; mq < 4; mq++){
        int r = wm0 + mq*16 + (lane & 15);
        aRow[mq] = r * 128; aS[mq] = r & 7;
    }
    uint32_t bRow[4], bS[4];
    const int bkb = (lane >> 3) & 1;
    #pragma unroll
    for (int nq = 0; nq < 4; nq++){
        int r = wn0 + nq*16 + (lane & 7) + ((lane & 16) ? 8 : 0);
        bRow[nq] = r * 128; bS[nq] = r & 7;
    }
    const int tKr = lane & 15;
    uint32_t tCk[4];
    #pragma unroll
    for (int nq = 0; nq < 4; nq++)
        tCk[nq] = (wn0 >> 3) + nq*2 + ((lane >> 4) & 1);

    float acc[4][8][4];
    #pragma unroll
    for (int a = 0; a < 4; a++)
        #pragma unroll
        for (int b = 0; b < 8; b++)
            #pragma unroll
            for (int c = 0; c < 4; c++) acc[a][b][c] = 0.f;

    auto compute = [&](int s){
        const uint32_t Ab = sb + s*stageB;
        const uint32_t Bb = Ab + TILEB;
        #pragma unroll
        for (int ks = 0; ks < 4; ks++){
            uint32_t ah[4][4], bh[16];
            #pragma unroll
            for (int mq = 0; mq < 4; mq++)
                ldsm4(ah[mq], Ab + aRow[mq] + ((uint32_t)((ks*2 + akb) ^ aS[mq]) << 4));
            if (TRB){
                const int kr = ks*16 + tKr;
                #pragma unroll
                for (int nq = 0; nq < 4; nq++)
                    ldsm4t(&bh[nq*4], Bb + kr*256 + ((tCk[nq] ^ (uint32_t)(kr & 7)) << 4));
            } else {
                #pragma unroll
                for (int nq = 0; nq < 4; nq++)
                    ldsm4(&bh[nq*4], Bb + bRow[nq] + ((uint32_t)((ks*2 + bkb) ^ bS[nq]) << 4));
            }
            #pragma unroll
            for (int mf = 0; mf < 4; mf++)
                #pragma unroll
                for (int nf = 0; nf < 8; nf++)
                    mma16816(acc[mf][nf], ah[mf], &bh[(nf>>1)*4 + (nf&1)*2]);
        }
    };

    // ---- pipelined mainloop (3-stage) ----
    #pragma unroll
    for (int s = 0; s < 2; s++)
        if (s < NITER) loadStage(s, s*64);
    for (int it = 0; it < NITER; ++it){
        if (it == NITER-1) cp_wait<0>();
        else               cp_wait<1>();
        __syncthreads();
        const int j = it + 2;
        if (j < NITER) loadStage(j % 3, j*64);
        compute(it % 3);
    }

    // ---- epilogue ----
    #pragma unroll
    for (int mf = 0; mf < 4; mf++){
        const int r = brow + wm0 + mf*16 + (lane >> 2);
        #pragma unroll
        for (int nf = 0; nf < 8; nf++){
            const int c = bcol + wn0 + nf*8 + (lane & 3)*2;
            float v[4];
            #pragma unroll
            for (int q = 0; q < 4; q++) v[q] = alpha * acc[mf][nf][q];
            if (BIASF){
                const float b0 = __ldg(bias + c), b1 = __ldg(bias + c + 1);
                v[0] += b0; v[1] += b1; v[2] += b0; v[3] += b1;
            }
            if (RELUF){
                #pragma unroll
                for (int q = 0; q < 4; q++) v[q] = fmaxf(v[q], 0.f);
            }
            if (RESF){
                v[0] += __ldg(Res + (long)r*ldres + c);
                v[1] += __ldg(Res + (long)r*ldres + c + 1);
                v[2] += __ldg(Res + (long)(r+8)*ldres + c);
                v[3] += __ldg(Res + (long)(r+8)*ldres + c + 1);
            }
            #pragma unroll
            for (int half = 0; half < 2; half++){
                const long o = (long)(r + half*8) * ldc + c;
                const float x0 = v[half*2], x1 = v[half*2 + 1];
                if (OUTM == 1){
                    float2 f; f.x = x0; f.y = x1;
                    *reinterpret_cast<float2*>(Cf + o) = f;
                } else if (OUTM == 0){
                    __nv_bfloat162 p;
                    p.x = __float2bfloat16(x0); p.y = __float2bfloat16(x1);
                    *reinterpret_cast<__nv_bfloat162*>(Ch + o) = p;
                } else {
                    float2 f; f.x = x0; f.y = x1;
                    *reinterpret_cast<float2*>(Cf + o) = f;
                    bf16 h0,l0,h1,l1;
                    split2(x0,h0,l0); split2(x1,h1,l1);
                    __nv_bfloat162 ph, pl;
                    ph.x = h0; ph.y = h1; pl.x = l0; pl.y = l1;
                    *reinterpret_cast<__nv_bfloat162*>(Ch + o) = ph;
                    *reinterpret_cast<__nv_bfloat162*>(Cl + o) = pl;
                }
            }
        }
    }
}

// ================= 3-pass GEMM (FFN), 64x32 warp tile, 256 threads =============
template<int OUTM, bool BIASF, bool RELUF, bool RESF, int STAGES>
__global__ void __launch_bounds__(256, 1)
gmma3p(int Kdim, float alpha,
       const bf16* __restrict__ Ah, const bf16* __restrict__ Al, int lda,
       const bf16* __restrict__ Bh, const bf16* __restrict__ Bl, int ldb,
       float* __restrict__ Cf, bf16* __restrict__ Ch, bf16* __restrict__ Cl,
       int ldc,
       const float* __restrict__ bias, const float* __restrict__ Res, int ldres)
{
    extern __shared__ char smem[];
    const uint32_t sb = s2u(smem);
    const int tid = threadIdx.x, wid = tid >> 5, lane = tid & 31;
    const int wm0 = (wid >> 2) * 64;
    const int wn0 = (wid & 3) * 32;

    const int brow = blockIdx.y * 128, bcol = blockIdx.x * 128;
    const int NITER = Kdim >> 6;
    const uint32_t stageB = 4 * TILEB;

    auto ldTile = [&](const bf16* g, int ld, int r0, int k0, uint32_t so){
        #pragma unroll
        for (int i = 0; i < 4; i++){
            int idx = i*256 + tid;
            int row = idx >> 3, c = idx & 7;
            cpasync16(sb + so + row*128 + (((c ^ (row&7)))<<4),
                      g + (long)(r0+row)*ld + k0 + c*8);
        }
    };
    auto ldTileT = [&](const bf16* g, int ld, int c0, int k0, uint32_t so){
        #pragma unroll
        for (int i = 0; i < 4; i++){
            int idx = i*256 + tid;
            int row = idx >> 4, c = idx & 15;
            cpasync16(sb + so + row*256 + (((c ^ (row&7)))<<4),
                      g + (long)(k0+row)*ld + c0 + c*8);
        }
    };
    auto loadStage = [&](int s, int k0){
        uint32_t so = s * stageB;
        ldTile(Ah, lda, brow, k0, so);
        ldTile(Al, lda, brow, k0, so + TILEB);
        ldTileT(Bh, ldb, bcol, k0, so + 2*TILEB);
        ldTileT(Bl, ldb, bcol, k0, so + 3*TILEB);
        cp_commit();
    };

    uint32_t aRow[4], aS[4];
    const int akb = (lane >> 4) & 1;
    #pragma unroll
    for (int mq = 0; mq < 4; mq++){
        int r = wm0 + mq*16 + (lane & 15);
        aRow[mq] = r * 128; aS[mq] = r & 7;
    }
    const int tKr = lane & 15;
    uint32_t tCk[2];
    #pragma unroll
    for (int nq = 0; nq < 2; nq++)
        tCk[nq] = (wn0 >> 3) + nq*2 + ((lane >> 4) & 1);

    float acc[4][4][4];
    #pragma unroll
    for (int a = 0; a < 4; a++)
        #pragma unroll
        for (int b = 0; b < 4; b++)
            #pragma unroll
            for (int c = 0; c < 4; c++) acc[a][b][c] = 0.f;

    auto compute = [&](int s){
        const uint32_t Ab  = sb + s*stageB;
        const uint32_t Alb = Ab + TILEB;
        const uint32_t Bb  = Ab + 2*TILEB;
        const uint32_t Blb = Ab + 3*TILEB;
        #pragma unroll
        for (int ks = 0; ks < 4; ks++){
            uint32_t ah[4][4], bh[8];
            const int kr = ks*16 + tKr;
            #pragma unroll
            for (int mq = 0; mq < 4; mq++)
                ldsm4(ah[mq], Ab + aRow[mq] + ((uint32_t)((ks*2 + akb) ^ aS[mq]) << 4));
            #pragma unroll
            for (int nq = 0; nq < 2; nq++)
                ldsm4t(&bh[nq*4], Bb + kr*256 + ((tCk[nq] ^ (uint32_t)(kr & 7)) << 4));
            #pragma unroll
            for (int mf = 0; mf < 4; mf++)
                #pragma unroll
                for (int nf = 0; nf < 4; nf++)
                    mma16816(acc[mf][nf], ah[mf], &bh[(nf>>1)*4 + (nf&1)*2]);

            uint32_t bl[8];
            #pragma unroll
            for (int nq = 0; nq < 2; nq++)
                ldsm4t(&bl[nq*4], Blb + kr*256 + ((tCk[nq] ^ (uint32_t)(kr & 7)) << 4));
            #pragma unroll
            for (int mf = 0; mf < 4; mf++)
                #pragma unroll
                for (int nf = 0; nf < 4; nf++)
                    mma16816(acc[mf][nf], ah[mf], &bl[(nf>>1)*4 + (nf&1)*2]);

            uint32_t al[4][4];
            #pragma unroll
            for (int mq = 0; mq < 4; mq++)
                ldsm4(al[mq], Alb + aRow[mq] + ((uint32_t)((ks*2 + akb) ^ aS[mq]) << 4));
            #pragma unroll
            for (int mf = 0; mf < 4; mf++)
                #pragma unroll
                for (int nf = 0; nf < 4; nf++)
                    mma16816(acc[mf][nf], al[mf], &bh[(nf>>1)*4 + (nf&1)*2]);
        }
    };

    #pragma unroll
    for (int s = 0; s < STAGES-1; s++)
        if (s < NITER) loadStage(s, s*64);
    for (int it = 0; it < NITER; ++it){
        if (it == NITER-1) cp_wait<0>();
        else               cp_wait<STAGES-2>();
        __syncthreads();
        const int j = it + STAGES - 1;
        if (j < NITER) loadStage(j % STAGES, j*64);
        compute(it % STAGES);
    }

    #pragma unroll
    for (int mf = 0; mf < 4; mf++){
        const int r = brow + wm0 + mf*16 + (lane >> 2);
        #pragma unroll
        for (int nf = 0; nf < 4; nf++){
            const int c = bcol + wn0 + nf*8 + (lane & 3)*2;
            float v[4];
            #pragma unroll
            for (int q = 0; q < 4; q++) v[q] = alpha * acc[mf][nf][q];
            if (BIASF){
                const float b0 = __ldg(bias + c), b1 = __ldg(bias + c + 1);
                v[0] += b0; v[1] += b1; v[2] += b0; v[3] += b1;
            }
            if (RELUF){
                #pragma unroll
                for (int q = 0; q < 4; q++) v[q] = fmaxf(v[q], 0.f);
            }
            if (RESF){
                v[0] += __ldg(Res + (long)r*ldres + c);
                v[1] += __ldg(Res + (long)r*ldres + c + 1);
                v[2] += __ldg(Res + (long)(r+8)*ldres + c);
                v[3] += __ldg(Res + (long)(r+8)*ldres + c + 1);
            }
            #pragma unroll
            for (int half = 0; half < 2; half++){
                const long o = (long)(r + half*8) * ldc + c;
                const float x0 = v[half*2], x1 = v[half*2 + 1];
                if (OUTM == 1){
                    float2 f; f.x = x0; f.y = x1;
                    *reinterpret_cast<float2*>(Cf + o) = f;
                } else {
                    bf16 h0,l0,h1,l1;
                    split2(x0,h0,l0); split2(x1,h1,l1);
                    __nv_bfloat162 ph, pl;
                    ph.x = h0; ph.y = h1; pl.x = l0; pl.y = l1;
                    *reinterpret_cast<__nv_bfloat162*>(Ch + o) = ph;
                    *reinterpret_cast<__nv_bfloat162*>(Cl + o) = pl;
                }
            }
        }
    }
}

// ---------------- register-resident causal softmax ----------------
__global__ void __launch_bounds__(256)
softmax_reg(const float* __restrict__ S, bf16* __restrict__ P, int T)
{
    const int q = blockIdx.x;
    const long ro = ((long)blockIdx.y * T + q) * T;
    const int n = q + 1;
    const int tid = threadIdx.x;
    __shared__ float sh[8];
    const int lane = tid & 31, wid = tid >> 5;

    float v[8];
    #pragma unroll
    for (int i = 0; i < 8; i++){
        const int j = tid + i*256;
        v[i] = (j < n) ? __ldg(S + ro + j) : -INFINITY;
    }
    float m = v[0];
    #pragma unroll
    for (int i = 1; i < 8; i++) m = fmaxf(m, v[i]);
    #pragma unroll
    for (int o = 16; o > 0; o >>= 1) m = fmaxf(m, __shfl_xor_sync(0xffffffffu, m, o));
    if (lane == 0) sh[wid] = m;
    __syncthreads();
    m = sh[lane & 7];
    #pragma unroll
    for (int o = 4; o > 0; o >>= 1) m = fmaxf(m, __shfl_xor_sync(0xffffffffu, m, o));

    float s = 0.f;
    #pragma unroll
    for (int i = 0; i < 8; i++){ v[i] = __expf(v[i] - m); s += v[i]; }
    #pragma unroll
    for (int o = 16; o > 0; o >>= 1) s += __shfl_xor_sync(0xffffffffu, s, o);
    __syncthreads();
    if (lane == 0) sh[wid] = s;
    __syncthreads();
    s = sh[0]+sh[1]+sh[2]+sh[3]+sh[4]+sh[5]+sh[6]+sh[7];
    const float inv = 1.f / s;

    #pragma unroll
    for (int i = 0; i < 8; i += 2){
        const int j = tid + i*256;
        P[ro + j] = __float2bfloat16(v[i] * inv);
        P[ro + j + 256] = __float2bfloat16(v[i+1] * inv);
    }
}

// ---------------- host ----------------
#define GETB(sym, var) bf16* var; cudaGetSymbolAddress((void**)&var, sym)

extern "C" void kernel_launch(void* const* d_in, const int* in_sizes, int n_in,
                              void* d_out, int out_size)
{
    (void)in_sizes; (void)n_in; (void)out_size;
    const float* x  = (const float*)d_in[0];
    const float* Wq = (const float*)d_in[1];
    const float* Wk = (const float*)d_in[2];
    const float* Wv = (const float*)d_in[3];
    const float* Wu = (const float*)d_in[4];
    const float* bu = (const float*)d_in[5];
    const float* W1 = (const float*)d_in[6];
    const float* b1 = (const float*)d_in[7];
    const float* W2 = (const float*)d_in[8];
    const float* b2 = (const float*)d_in[9];
    float* out = (float*)d_out;

    GETB(g_Xb,Xb);
    GETB(g_Wqb,Wqb); GETB(g_Wkb,Wkb); GETB(g_Wvb,Wvb); GETB(g_Wub,Wub);
    GETB(g_W1h,W1h); GETB(g_W1l,W1l); GETB(g_W2h,W2h); GETB(g_W2l,W2l);
    GETB(g_Q,Q); GETB(g_K,Kb); GETB(g_V,V);
    GETB(g_P,P); GETB(g_O,O);
    GETB(g_X1h,X1h); GETB(g_X1l,X1l); GETB(g_Hh,Hh); GETB(g_Hl,Hl);
    float *S, *X1;
    cudaGetSymbolAddress((void**)&S,  g_S);
    cudaGetSymbolAddress((void**)&X1, g_X1);

    // single-pass (64x64 warp tile, 128 thr, 2 CTA/SM)
    auto gQKV = gmma64<true ,0,false,false,false,false,false,3>;
    auto gS   = gmma64<false,1,false,false,false,true ,false,1>;
    auto gPV  = gmma64<true ,0,false,false,false,false,true ,1>;
    auto gWu  = gmma64<true ,2,true ,false,true ,false,false,1>;
    // 3-pass FFN (64x32 warp tile, 256 thr)
    auto gF1  = gmma3p<0,true ,true ,false,2>;
    auto gF2  = gmma3p<1,true ,false,true ,2>;

    const int SM1 = 3*2*TILEB;   // 96 KB
    const int SM3 = 2*4*TILEB;   // 128 KB
    cudaFuncSetAttribute(gQKV, cudaFuncAttributeMaxDynamicSharedMemorySize, SM1);
    cudaFuncSetAttribute(gS  , cudaFuncAttributeMaxDynamicSharedMemorySize, SM1);
    cudaFuncSetAttribute(gPV , cudaFuncAttributeMaxDynamicSharedMemorySize, SM1);
    cudaFuncSetAttribute(gWu , cudaFuncAttributeMaxDynamicSharedMemorySize, SM1);
    cudaFuncSetAttribute(gF1 , cudaFuncAttributeMaxDynamicSharedMemorySize, SM3);
    cudaFuncSetAttribute(gF2 , cudaFuncAttributeMaxDynamicSharedMemorySize, SM3);

    // ---- 0. dtype conversions ----
    conv5<<<5*256, 256>>>(x, Xb, Wq, Wqb, Wk, Wkb, Wv, Wvb, Wu, Wub);
    conv_hl2<<<2*64, 256>>>(W1, W1h, W1l, W2, W2h, W2l);

    const long sTT = (long)TSEQ*TSEQ;

    // ---- 1. fused Q,K,V projections ----
    gQKV<<<dim3(DPROJ/128, NTOK/128, 3), 128, SM1>>>(
        DK, 1.f, Xb, DK, 0, 0,
        Wqb, DPROJ, 0, 0, Wkb, Wvb,
        nullptr, Q, nullptr, Kb, V, DPROJ, 0, 0,
        nullptr, nullptr, 0, 1);

    // ---- 2. S = (1/32) Q K^T, triangular block launch ----
    {
        const int nb = TSEQ/128;
        gS<<<dim3(nb*(nb+1)/2, 1, BSZ*HH), 128, SM1>>>(
            DK, 0.03125f,
            Q,  DPROJ, (long)TSEQ*DPROJ, DK,
            Kb, DPROJ, (long)TSEQ*DPROJ, DK,
            nullptr, nullptr,
            S, nullptr, nullptr, nullptr, nullptr, TSEQ, (long)HH*sTT, sTT,
            nullptr, nullptr, 0, HH);
    }

    // ---- 3. softmax -> P bf16 ----
    softmax_reg<<<dim3(TSEQ, BSZ*HH), 256>>>(S, P, TSEQ);

    // ---- 4. O = P @ V, causal K bound ----
    gPV<<<dim3(DK/128, TSEQ/128, BSZ*HH), 128, SM1>>>(
        TSEQ, 1.f,
        P, TSEQ, (long)HH*sTT, sTT,
        V, DPROJ, (long)TSEQ*DPROJ, DK,
        nullptr, nullptr,
        nullptr, O, nullptr, nullptr, nullptr, DPROJ, (long)TSEQ*DPROJ, DK,
        nullptr, nullptr, 0, HH);

    // ---- 5. X1 = x + O@Wu + bu ----
    gWu<<<dim3(DK/128, NTOK/128, 1), 128, SM1>>>(
        DPROJ, 1.f, O, DPROJ, 0, 0,
        Wub, DK, 0, 0, nullptr, nullptr,
        X1, X1h, X1l, nullptr, nullptr, DK, 0, 0, bu, x, DK, 1);

    // ---- 6. H = relu(X1@W1 + b1)  (3-pass) ----
    gF1<<<dim3(DK/128, NTOK/128, 1), 256, SM3>>>(
        DK, 1.f, X1h, X1l, DK,
        W1h, W1l, DK,
        nullptr, Hh, Hl, DK, b1, nullptr, 0);

    // ---- 7. out = X1 + H@W2 + b2  (3-pass) ----
    gF2<<<dim3(DK/128, NTOK/128, 1), 256, SM3>>>(
        DK, 1.f, Hh, Hl, DK,
        W2h, W2l, DK,
        out, nullptr, nullptr, DK, b2, X1, DK);
}

// round 9
// speedup vs baseline: 8.9229x; 1.0703x over previous
#include <cuda_runtime.h>
#include <cuda_bf16.h>
#include <stdint.h>
#include <math.h>

#define BSZ 2
#define TSEQ 2048
#define DK 1024
#define HH 4
#define NTOK (BSZ*TSEQ)      // 4096
#define DPROJ (HH*DK)        // 4096
typedef __nv_bfloat16 bf16;

// ---------------- scratch ----------------
__device__ bf16 g_Xb [(size_t)NTOK*DK];
__device__ bf16 g_Wqb[(size_t)DK*DPROJ];
__device__ bf16 g_Wkb[(size_t)DK*DPROJ];
__device__ bf16 g_Wvb[(size_t)DK*DPROJ];
__device__ bf16 g_Wub[(size_t)DPROJ*DK];
__device__ bf16 g_W1b[(size_t)DK*DK];
__device__ bf16 g_W2b[(size_t)DK*DK];
__device__ bf16 g_Q[(size_t)NTOK*DPROJ];
__device__ bf16 g_K[(size_t)NTOK*DPROJ];
__device__ bf16 g_V[(size_t)NTOK*DPROJ];
__device__ float g_S[(size_t)BSZ*HH*TSEQ*TSEQ];
__device__ bf16  g_P[(size_t)BSZ*HH*TSEQ*TSEQ];
__device__ bf16 g_O[(size_t)NTOK*DPROJ];
__device__ float g_X1[(size_t)NTOK*DK];
__device__ bf16 g_X1h[(size_t)NTOK*DK], g_X1l[(size_t)NTOK*DK];
__device__ bf16 g_Hh[(size_t)NTOK*DK],  g_Hl[(size_t)NTOK*DK];

// ---------------- PTX helpers ----------------
static __device__ __forceinline__ uint32_t s2u(const void* p){
    uint32_t a;
    asm("{ .reg .u64 t; cvta.to.shared.u64 t, %1; cvt.u32.u64 %0, t; }" : "=r"(a) : "l"(p));
    return a;
}
static __device__ __forceinline__ void cpasync16(uint32_t dst, const void* src){
    asm volatile("cp.async.cg.shared.global [%0], [%1], 16;"
                 :: "r"(dst), "l"(__cvta_generic_to_global(src)) : "memory");
}
static __device__ __forceinline__ void cp_commit(){
    asm volatile("cp.async.commit_group;" ::: "memory");
}
template<int N>
static __device__ __forceinline__ void cp_wait(){
    asm volatile("cp.async.wait_group %0;" :: "n"(N) : "memory");
}
static __device__ __forceinline__ void ldsm4(uint32_t* r, uint32_t a){
    asm volatile("ldmatrix.sync.aligned.m8n8.x4.shared.b16 {%0,%1,%2,%3}, [%4];"
                 : "=r"(r[0]),"=r"(r[1]),"=r"(r[2]),"=r"(r[3]) : "r"(a));
}
static __device__ __forceinline__ void ldsm4t(uint32_t* r, uint32_t a){
    asm volatile("ldmatrix.sync.aligned.m8n8.x4.trans.shared.b16 {%0,%1,%2,%3}, [%4];"
                 : "=r"(r[0]),"=r"(r[1]),"=r"(r[2]),"=r"(r[3]) : "r"(a));
}
static __device__ __forceinline__ void mma16816(float* c, const uint32_t* a, const uint32_t* b){
    asm volatile(
        "mma.sync.aligned.m16n8k16.row.col.f32.bf16.bf16.f32 "
        "{%0,%1,%2,%3}, {%4,%5,%6,%7}, {%8,%9}, {%0,%1,%2,%3};"
        : "+f"(c[0]),"+f"(c[1]),"+f"(c[2]),"+f"(c[3])
        : "r"(a[0]),"r"(a[1]),"r"(a[2]),"r"(a[3]), "r"(b[0]),"r"(b[1]));
}
static __device__ __forceinline__ void split2(float v, bf16& h, bf16& l){
    h = __float2bfloat16(v);
    l = __float2bfloat16(v - __bfloat162float(h));
}

// ---------------- fused conversion kernels ----------------
__global__ void __launch_bounds__(256)
conv5(const float* __restrict__ s0, bf16* __restrict__ d0,
      const float* __restrict__ s1, bf16* __restrict__ d1,
      const float* __restrict__ s2, bf16* __restrict__ d2,
      const float* __restrict__ s3, bf16* __restrict__ d3,
      const float* __restrict__ s4, bf16* __restrict__ d4)
{
    const int seg = blockIdx.x >> 8, b = blockIdx.x & 255;
    const float* s; bf16* d;
    switch (seg){
        case 0: s = s0; d = d0; break;
        case 1: s = s1; d = d1; break;
        case 2: s = s2; d = d2; break;
        case 3: s = s3; d = d3; break;
        default: s = s4; d = d4; break;
    }
    const int base = b * (256*16);
    #pragma unroll 4
    for (int i = 0; i < 16; i++){
        int idx = base + i*256 + threadIdx.x;
        float4 v = reinterpret_cast<const float4*>(s)[idx];
        __nv_bfloat162 a, c;
        a.x = __float2bfloat16(v.x); a.y = __float2bfloat16(v.y);
        c.x = __float2bfloat16(v.z); c.y = __float2bfloat16(v.w);
        reinterpret_cast<__nv_bfloat162*>(d)[2*idx]   = a;
        reinterpret_cast<__nv_bfloat162*>(d)[2*idx+1] = c;
    }
}
// 2 segments x 1M fp32 -> plain bf16 (FFN weights)
__global__ void __launch_bounds__(256)
conv2(const float* __restrict__ s0, bf16* __restrict__ d0,
      const float* __restrict__ s1, bf16* __restrict__ d1)
{
    const int seg = blockIdx.x >> 6, b = blockIdx.x & 63;
    const float* s = seg ? s1 : s0;
    bf16* d = seg ? d1 : d0;
    const int base = b * (256*16);
    #pragma unroll 4
    for (int i = 0; i < 16; i++){
        int idx = base + i*256 + threadIdx.x;
        float4 v = reinterpret_cast<const float4*>(s)[idx];
        __nv_bfloat162 a, c;
        a.x = __float2bfloat16(v.x); a.y = __float2bfloat16(v.y);
        c.x = __float2bfloat16(v.z); c.y = __float2bfloat16(v.w);
        reinterpret_cast<__nv_bfloat162*>(d)[2*idx]   = a;
        reinterpret_cast<__nv_bfloat162*>(d)[2*idx+1] = c;
    }
}

// ================= single-pass GEMM, 64x64 warp tile, 128 threads ==============
// CTA tile 128x128, warps 2x2 (each 64x64), 3-stage cp.async, 2 CTAs/SM.
#define TILEB 16384   // 128x64 bf16 (or 64x128 for TRB)

template<bool TRB, int OUTM, bool BIASF, bool RELUF, bool RESF,
         bool CSKIP, bool CK, int NSEL>
__global__ void __launch_bounds__(128, 2)
gmma64(int Kdim, float alpha,
       const bf16* __restrict__ Ah, int lda, long sAo, long sAi,
       const bf16* __restrict__ Bh, int ldb, long sBo, long sBi,
       const bf16* __restrict__ Bh2, const bf16* __restrict__ Bh3,
       float* __restrict__ Cf, bf16* __restrict__ Ch, bf16* __restrict__ Cl,
       bf16* __restrict__ Ch2, bf16* __restrict__ Ch3,
       int ldc, long sCo, long sCi,
       const float* __restrict__ bias, const float* __restrict__ Res, int ldres,
       int innerCount)
{
    extern __shared__ char smem[];
    const uint32_t sb = s2u(smem);
    const int tid = threadIdx.x, wid = tid >> 5, lane = tid & 31;
    const int wm0 = (wid >> 1) * 64;
    const int wn0 = (wid & 1) * 64;

    int bxi, byi;
    if (CSKIP){
        const int i = blockIdx.x;
        int y = (int)((sqrtf(8.f*(float)i + 1.f) - 1.f) * 0.5f);
        while ((y+1)*(y+2)/2 <= i) y++;
        while (y*(y+1)/2 > i) y--;
        byi = y; bxi = i - y*(y+1)/2;
    } else {
        bxi = blockIdx.x; byi = blockIdx.y;
    }

    if (NSEL == 3){
        const int sel = blockIdx.z;
        if (sel == 1){ Bh = Bh2; Ch = Ch2; }
        else if (sel == 2){ Bh = Bh3; Ch = Ch3; }
    } else {
        const int z = blockIdx.z, zo = z / innerCount, zi = z - zo * innerCount;
        Ah += zo*sAo + (long)zi*sAi;
        Bh += zo*sBo + (long)zi*sBi;
        const long coff = zo*sCo + (long)zi*sCi;
        if (Cf) Cf += coff;
        if (Ch) Ch += coff;
        if (Cl) Cl += coff;
    }

    const int brow = byi * 128, bcol = bxi * 128;
    const int kEnd = CK ? (byi + 1) * 128 : Kdim;
    const int NITER = kEnd >> 6;
    const uint32_t stageB = 2 * TILEB;

    auto ldTile = [&](const bf16* g, int ld, int r0, int k0, uint32_t so){
        #pragma unroll
        for (int i = 0; i < 8; i++){
            int idx = i*128 + tid;
            int row = idx >> 3, c = idx & 7;
            cpasync16(sb + so + row*128 + (((c ^ (row&7)))<<4),
                      g + (long)(r0+row)*ld + k0 + c*8);
        }
    };
    auto ldTileT = [&](const bf16* g, int ld, int c0, int k0, uint32_t so){
        #pragma unroll
        for (int i = 0; i < 8; i++){
            int idx = i*128 + tid;
            int row = idx >> 4, c = idx & 15;
            cpasync16(sb + so + row*256 + (((c ^ (row&7)))<<4),
                      g + (long)(k0+row)*ld + c0 + c*8);
        }
    };
    auto loadStage = [&](int s, int k0){
        uint32_t so = s * stageB;
        ldTile(Ah, lda, brow, k0, so);
        if (TRB) ldTileT(Bh, ldb, bcol, k0, so + TILEB);
        else     ldTile (Bh, ldb, bcol, k0, so + TILEB);
        cp_commit();
    };

    uint32_t aRow[4], aS[4];
    const int akb = (lane >> 4) & 1;
    #pragma unroll
    for (int mq = 0; mq < 4; mq++){
        int r = wm0 + mq*16 + (lane & 15);
        aRow[mq] = r * 128; aS[mq] = r & 7;
    }
    uint32_t bRow[4], bS[4];
    const int bkb = (lane >> 3) & 1;
    #pragma unroll
    for (int nq = 0; nq < 4; nq++){
        int r = wn0 + nq*16 + (lane & 7) + ((lane & 16) ? 8 : 0);
        bRow[nq] = r * 128; bS[nq] = r & 7;
    }
    const int tKr = lane & 15;
    uint32_t tCk[4];
    #pragma unroll
    for (int nq = 0; nq < 4; nq++)
        tCk[nq] = (wn0 >> 3) + nq*2 + ((lane >> 4) & 1);

    float acc[4][8][4];
    #pragma unroll
    for (int a = 0; a < 4; a++)
        #pragma unroll
        for (int b = 0; b < 8; b++)
            #pragma unroll
            for (int c = 0; c < 4; c++) acc[a][b][c] = 0.f;

    auto compute = [&](int s){
        const uint32_t Ab = sb + s*stageB;
        const uint32_t Bb = Ab + TILEB;
        #pragma unroll
        for (int ks = 0; ks < 4; ks++){
            uint32_t ah[4][4], bh[16];
            #pragma unroll
            for (int mq = 0; mq < 4; mq++)
                ldsm4(ah[mq], Ab + aRow[mq] + ((uint32_t)((ks*2 + akb) ^ aS[mq]) << 4));
            if (TRB){
                const int kr = ks*16 + tKr;
                #pragma unroll
                for (int nq = 0; nq < 4; nq++)
                    ldsm4t(&bh[nq*4], Bb + kr*256 + ((tCk[nq] ^ (uint32_t)(kr & 7)) << 4));
            } else {
                #pragma unroll
                for (int nq = 0; nq < 4; nq++)
                    ldsm4(&bh[nq*4], Bb + bRow[nq] + ((uint32_t)((ks*2 + bkb) ^ bS[nq]) << 4));
            }
            #pragma unroll
            for (int mf = 0; mf < 4; mf++)
                #pragma unroll
                for (int nf = 0; nf < 8; nf++)
                    mma16816(acc[mf][nf], ah[mf], &bh[(nf>>1)*4 + (nf&1)*2]);
        }
    };

    #pragma unroll
    for (int s = 0; s < 2; s++)
        if (s < NITER) loadStage(s, s*64);
    for (int it = 0; it < NITER; ++it){
        if (it == NITER-1) cp_wait<0>();
        else               cp_wait<1>();
        __syncthreads();
        const int j = it + 2;
        if (j < NITER) loadStage(j % 3, j*64);
        compute(it % 3);
    }

    #pragma unroll
    for (int mf = 0; mf < 4; mf++){
        const int r = brow + wm0 + mf*16 + (lane >> 2);
        #pragma unroll
        for (int nf = 0; nf < 8; nf++){
            const int c = bcol + wn0 + nf*8 + (lane & 3)*2;
            float v[4];
            #pragma unroll
            for (int q = 0; q < 4; q++) v[q] = alpha * acc[mf][nf][q];
            if (BIASF){
                const float b0 = __ldg(bias + c), b1 = __ldg(bias + c + 1);
                v[0] += b0; v[1] += b1; v[2] += b0; v[3] += b1;
            }
            if (RELUF){
                #pragma unroll
                for (int q = 0; q < 4; q++) v[q] = fmaxf(v[q], 0.f);
            }
            if (RESF){
                v[0] += __ldg(Res + (long)r*ldres + c);
                v[1] += __ldg(Res + (long)r*ldres + c + 1);
                v[2] += __ldg(Res + (long)(r+8)*ldres + c);
                v[3] += __ldg(Res + (long)(r+8)*ldres + c + 1);
            }
            #pragma unroll
            for (int half = 0; half < 2; half++){
                const long o = (long)(r + half*8) * ldc + c;
                const float x0 = v[half*2], x1 = v[half*2 + 1];
                if (OUTM == 1){
                    float2 f; f.x = x0; f.y = x1;
                    *reinterpret_cast<float2*>(Cf + o) = f;
                } else if (OUTM == 0){
                    __nv_bfloat162 p;
                    p.x = __float2bfloat16(x0); p.y = __float2bfloat16(x1);
                    *reinterpret_cast<__nv_bfloat162*>(Ch + o) = p;
                } else {
                    float2 f; f.x = x0; f.y = x1;
                    *reinterpret_cast<float2*>(Cf + o) = f;
                    bf16 h0,l0,h1,l1;
                    split2(x0,h0,l0); split2(x1,h1,l1);
                    __nv_bfloat162 ph, pl;
                    ph.x = h0; ph.y = h1; pl.x = l0; pl.y = l1;
                    *reinterpret_cast<__nv_bfloat162*>(Ch + o) = ph;
                    *reinterpret_cast<__nv_bfloat162*>(Cl + o) = pl;
                }
            }
        }
    }
}

// ========== 2-pass FFN GEMM: C = (Ah+Al) @ B  (B plain bf16 [K,N]) ============
// 64x64 warp tile, 128 threads, 2-stage (48KB/stage), 2 CTAs/SM.
// OUTM: 1 = fp32; 3 = bf16 hi/lo.
template<int OUTM, bool BIASF, bool RELUF, bool RESF>
__global__ void __launch_bounds__(128, 2)
gmma64_2A(int Kdim, float alpha,
          const bf16* __restrict__ Ah, const bf16* __restrict__ Al, int lda,
          const bf16* __restrict__ Bh, int ldb,
          float* __restrict__ Cf, bf16* __restrict__ Ch, bf16* __restrict__ Cl,
          int ldc,
          const float* __restrict__ bias, const float* __restrict__ Res, int ldres)
{
    extern __shared__ char smem[];
    const uint32_t sb = s2u(smem);
    const int tid = threadIdx.x, wid = tid >> 5, lane = tid & 31;
    const int wm0 = (wid >> 1) * 64;
    const int wn0 = (wid & 1) * 64;

    const int brow = blockIdx.y * 128, bcol = blockIdx.x * 128;
    const int NITER = Kdim >> 6;
    const uint32_t stageB = 3 * TILEB;   // Ah + Al + B

    auto ldTile = [&](const bf16* g, int ld, int r0, int k0, uint32_t so){
        #pragma unroll
        for (int i = 0; i < 8; i++){
            int idx = i*128 + tid;
            int row = idx >> 3, c = idx & 7;
            cpasync16(sb + so + row*128 + (((c ^ (row&7)))<<4),
                      g + (long)(r0+row)*ld + k0 + c*8);
        }
    };
    auto ldTileT = [&](const bf16* g, int ld, int c0, int k0, uint32_t so){
        #pragma unroll
        for (int i = 0; i < 8; i++){
            int idx = i*128 + tid;
            int row = idx >> 4, c = idx & 15;
            cpasync16(sb + so + row*256 + (((c ^ (row&7)))<<4),
                      g + (long)(k0+row)*ld + c0 + c*8);
        }
    };
    auto loadStage = [&](int s, int k0){
        uint32_t so = s * stageB;
        ldTile(Ah, lda, brow, k0, so);
        ldTile(Al, lda, brow, k0, so + TILEB);
        ldTileT(Bh, ldb, bcol, k0, so + 2*TILEB);
        cp_commit();
    };

    uint32_t aRow[4], aS[4];
    const int akb = (lane >> 4) & 1;
    #pragma unroll
    for (int mq = 0; mq < 4; mq++){
        int r = wm0 + mq*16 + (lane & 15);
        aRow[mq] = r * 128; aS[mq] = r & 7;
    }
    const int tKr = lane & 15;
    uint32_t tCk[4];
    #pragma unroll
    for (int nq = 0; nq < 4; nq++)
        tCk[nq] = (wn0 >> 3) + nq*2 + ((lane >> 4) & 1);

    float acc[4][8][4];
    #pragma unroll
    for (int a = 0; a < 4; a++)
        #pragma unroll
        for (int b = 0; b < 8; b++)
            #pragma unroll
            for (int c = 0; c < 4; c++) acc[a][b][c] = 0.f;

    auto compute = [&](int s){
        const uint32_t Ab  = sb + s*stageB;
        const uint32_t Alb = Ab + TILEB;
        const uint32_t Bb  = Ab + 2*TILEB;
        #pragma unroll
        for (int ks = 0; ks < 4; ks++){
            uint32_t ah[4][4], bh[16];
            const int kr = ks*16 + tKr;
            #pragma unroll
            for (int mq = 0; mq < 4; mq++)
                ldsm4(ah[mq], Ab + aRow[mq] + ((uint32_t)((ks*2 + akb) ^ aS[mq]) << 4));
            #pragma unroll
            for (int nq = 0; nq < 4; nq++)
                ldsm4t(&bh[nq*4], Bb + kr*256 + ((tCk[nq] ^ (uint32_t)(kr & 7)) << 4));
            #pragma unroll
            for (int mf = 0; mf < 4; mf++)
                #pragma unroll
                for (int nf = 0; nf < 8; nf++)
                    mma16816(acc[mf][nf], ah[mf], &bh[(nf>>1)*4 + (nf&1)*2]);

            uint32_t al[4][4];
            #pragma unroll
            for (int mq = 0; mq < 4; mq++)
                ldsm4(al[mq], Alb + aRow[mq] + ((uint32_t)((ks*2 + akb) ^ aS[mq]) << 4));
            #pragma unroll
            for (int mf = 0; mf < 4; mf++)
                #pragma unroll
                for (int nf = 0; nf < 8; nf++)
                    mma16816(acc[mf][nf], al[mf], &bh[(nf>>1)*4 + (nf&1)*2]);
        }
    };

    // 2-stage pipeline
    if (0 < NITER) loadStage(0, 0);
    for (int it = 0; it < NITER; ++it){
        cp_wait<0>();
        __syncthreads();
        if (it + 1 < NITER) loadStage((it+1) & 1, (it+1)*64);
        compute(it & 1);
    }

    #pragma unroll
    for (int mf = 0; mf < 4; mf++){
        const int r = brow + wm0 + mf*16 + (lane >> 2);
        #pragma unroll
        for (int nf = 0; nf < 8; nf++){
            const int c = bcol + wn0 + nf*8 + (lane & 3)*2;
            float v[4];
            #pragma unroll
            for (int q = 0; q < 4; q++) v[q] = alpha * acc[mf][nf][q];
            if (BIASF){
                const float b0 = __ldg(bias + c), b1 = __ldg(bias + c + 1);
                v[0] += b0; v[1] += b1; v[2] += b0; v[3] += b1;
            }
            if (RELUF){
                #pragma unroll
                for (int q = 0; q < 4; q++) v[q] = fmaxf(v[q], 0.f);
            }
            if (RESF){
                v[0] += __ldg(Res + (long)r*ldres + c);
                v[1] += __ldg(Res + (long)r*ldres + c + 1);
                v[2] += __ldg(Res + (long)(r+8)*ldres + c);
                v[3] += __ldg(Res + (long)(r+8)*ldres + c + 1);
            }
            #pragma unroll
            for (int half = 0; half < 2; half++){
                const long o = (long)(r + half*8) * ldc + c;
                const float x0 = v[half*2], x1 = v[half*2 + 1];
                if (OUTM == 1){
                    float2 f; f.x = x0; f.y = x1;
                    *reinterpret_cast<float2*>(Cf + o) = f;
                } else {
                    bf16 h0,l0,h1,l1;
                    split2(x0,h0,l0); split2(x1,h1,l1);
                    __nv_bfloat162 ph, pl;
                    ph.x = h0; ph.y = h1; pl.x = l0; pl.y = l1;
                    *reinterpret_cast<__nv_bfloat162*>(Ch + o) = ph;
                    *reinterpret_cast<__nv_bfloat162*>(Cl + o) = pl;
                }
            }
        }
    }
}

// ---------------- register-resident causal softmax ----------------
__global__ void __launch_bounds__(256)
softmax_reg(const float* __restrict__ S, bf16* __restrict__ P, int T)
{
    const int q = blockIdx.x;
    const long ro = ((long)blockIdx.y * T + q) * T;
    const int n = q + 1;
    const int tid = threadIdx.x;
    __shared__ float sh[8];
    const int lane = tid & 31, wid = tid >> 5;

    float v[8];
    #pragma unroll
    for (int i = 0; i < 8; i++){
        const int j = tid + i*256;
        v[i] = (j < n) ? __ldg(S + ro + j) : -INFINITY;
    }
    float m = v[0];
    #pragma unroll
    for (int i = 1; i < 8; i++) m = fmaxf(m, v[i]);
    #pragma unroll
    for (int o = 16; o > 0; o >>= 1) m = fmaxf(m, __shfl_xor_sync(0xffffffffu, m, o));
    if (lane == 0) sh[wid] = m;
    __syncthreads();
    m = sh[lane & 7];
    #pragma unroll
    for (int o = 4; o > 0; o >>= 1) m = fmaxf(m, __shfl_xor_sync(0xffffffffu, m, o));

    float s = 0.f;
    #pragma unroll
    for (int i = 0; i < 8; i++){ v[i] = __expf(v[i] - m); s += v[i]; }
    #pragma unroll
    for (int o = 16; o > 0; o >>= 1) s += __shfl_xor_sync(0xffffffffu, s, o);
    __syncthreads();
    if (lane == 0) sh[wid] = s;
    __syncthreads();
    s = sh[0]+sh[1]+sh[2]+sh[3]+sh[4]+sh[5]+sh[6]+sh[7];
    const float inv = 1.f / s;

    #pragma unroll
    for (int i = 0; i < 8; i += 2){
        const int j = tid + i*256;
        P[ro + j] = __float2bfloat16(v[i] * inv);
        P[ro + j + 256] = __float2bfloat16(v[i+1] * inv);
    }
}

// ---------------- host ----------------
#define GETB(sym, var) bf16* var; cudaGetSymbolAddress((void**)&var, sym)

extern "C" void kernel_launch(void* const* d_in, const int* in_sizes, int n_in,
                              void* d_out, int out_size)
{
    (void)in_sizes; (void)n_in; (void)out_size;
    const float* x  = (const float*)d_in[0];
    const float* Wq = (const float*)d_in[1];
    const float* Wk = (const float*)d_in[2];
    const float* Wv = (const float*)d_in[3];
    const float* Wu = (const float*)d_in[4];
    const float* bu = (const float*)d_in[5];
    const float* W1 = (const float*)d_in[6];
    const float* b1 = (const float*)d_in[7];
    const float* W2 = (const float*)d_in[8];
    const float* b2 = (const float*)d_in[9];
    float* out = (float*)d_out;

    GETB(g_Xb,Xb);
    GETB(g_Wqb,Wqb); GETB(g_Wkb,Wkb); GETB(g_Wvb,Wvb); GETB(g_Wub,Wub);
    GETB(g_W1b,W1b); GETB(g_W2b,W2b);
    GETB(g_Q,Q); GETB(g_K,Kb); GETB(g_V,V);
    GETB(g_P,P); GETB(g_O,O);
    GETB(g_X1h,X1h); GETB(g_X1l,X1l); GETB(g_Hh,Hh); GETB(g_Hl,Hl);
    float *S, *X1;
    cudaGetSymbolAddress((void**)&S,  g_S);
    cudaGetSymbolAddress((void**)&X1, g_X1);

    // single-pass (64x64 warp tile, 128 thr, 2 CTA/SM)
    auto gQKV = gmma64<true ,0,false,false,false,false,false,3>;
    auto gS   = gmma64<false,1,false,false,false,true ,false,1>;
    auto gPV  = gmma64<true ,0,false,false,false,false,true ,1>;
    auto gWu  = gmma64<true ,2,true ,false,true ,false,false,1>;
    // 2-pass FFN (activation hi/lo, weight plain bf16)
    auto gF1  = gmma64_2A<3,true ,true ,false>;
    auto gF2  = gmma64_2A<1,true ,false,true >;

    const int SM1 = 3*2*TILEB;   // 96 KB (3-stage single-pass)
    const int SM2 = 2*3*TILEB;   // 96 KB (2-stage 2-pass)
    cudaFuncSetAttribute(gQKV, cudaFuncAttributeMaxDynamicSharedMemorySize, SM1);
    cudaFuncSetAttribute(gS  , cudaFuncAttributeMaxDynamicSharedMemorySize, SM1);
    cudaFuncSetAttribute(gPV , cudaFuncAttributeMaxDynamicSharedMemorySize, SM1);
    cudaFuncSetAttribute(gWu , cudaFuncAttributeMaxDynamicSharedMemorySize, SM1);
    cudaFuncSetAttribute(gF1 , cudaFuncAttributeMaxDynamicSharedMemorySize, SM2);
    cudaFuncSetAttribute(gF2 , cudaFuncAttributeMaxDynamicSharedMemorySize, SM2);

    // ---- 0. dtype conversions ----
    conv5<<<5*256, 256>>>(x, Xb, Wq, Wqb, Wk, Wkb, Wv, Wvb, Wu, Wub);
    conv2<<<2*64, 256>>>(W1, W1b, W2, W2b);

    const long sTT = (long)TSEQ*TSEQ;

    // ---- 1. fused Q,K,V projections ----
    gQKV<<<dim3(DPROJ/128, NTOK/128, 3), 128, SM1>>>(
        DK, 1.f, Xb, DK, 0, 0,
        Wqb, DPROJ, 0, 0, Wkb, Wvb,
        nullptr, Q, nullptr, Kb, V, DPROJ, 0, 0,
        nullptr, nullptr, 0, 1);

    // ---- 2. S = (1/32) Q K^T, triangular block launch ----
    {
        const int nb = TSEQ/128;
        gS<<<dim3(nb*(nb+1)/2, 1, BSZ*HH), 128, SM1>>>(
            DK, 0.03125f,
            Q,  DPROJ, (long)TSEQ*DPROJ, DK,
            Kb, DPROJ, (long)TSEQ*DPROJ, DK,
            nullptr, nullptr,
            S, nullptr, nullptr, nullptr, nullptr, TSEQ, (long)HH*sTT, sTT,
            nullptr, nullptr, 0, HH);
    }

    // ---- 3. softmax -> P bf16 ----
    softmax_reg<<<dim3(TSEQ, BSZ*HH), 256>>>(S, P, TSEQ);

    // ---- 4. O = P @ V, causal K bound ----
    gPV<<<dim3(DK/128, TSEQ/128, BSZ*HH), 128, SM1>>>(
        TSEQ, 1.f,
        P, TSEQ, (long)HH*sTT, sTT,
        V, DPROJ, (long)TSEQ*DPROJ, DK,
        nullptr, nullptr,
        nullptr, O, nullptr, nullptr, nullptr, DPROJ, (long)TSEQ*DPROJ, DK,
        nullptr, nullptr, 0, HH);

    // ---- 5. X1 = x + O@Wu + bu  (fp32 + hi/lo) ----
    gWu<<<dim3(DK/128, NTOK/128, 1), 128, SM1>>>(
        DPROJ, 1.f, O, DPROJ, 0, 0,
        Wub, DK, 0, 0, nullptr, nullptr,
        X1, X1h, X1l, nullptr, nullptr, DK, 0, 0, bu, x, DK, 1);

    // ---- 6. H = relu((X1h+X1l)@W1 + b1)  (2-pass) -> hi/lo ----
    gF1<<<dim3(DK/128, NTOK/128, 1), 128, SM2>>>(
        DK, 1.f, X1h, X1l, DK,
        W1b, DK,
        nullptr, Hh, Hl, DK, b1, nullptr, 0);

    // ---- 7. out = X1 + (Hh+Hl)@W2 + b2  (2-pass) ----
    gF2<<<dim3(DK/128, NTOK/128, 1), 128, SM2>>>(
        DK, 1.f, Hh, Hl, DK,
        W2b, DK,
        out, nullptr, nullptr, DK, b2, X1, DK);
}